// round 7
// baseline (speedup 1.0000x reference)
#include <cuda_runtime.h>
#include <math.h>
#include <stdint.h>

// ---------------- problem constants ----------------
#define Bn 2
#define Tn 2048
#define NH 16
#define NKV 4
#define HD 128
#define DMODEL 2048
#define KVDIM 512
#define QKVSTR 3072         // combined QKV row: Q[0:2048) K[2048:2560) V[2560:3072)
#define ROWS 4096           // Bn*Tn
#define GK 2048             // K dim of every GEMM

// ---------------- scratch (__device__ globals) ----------------
__device__ float g_xr  [(size_t)ROWS * DMODEL];   // tf32-rounded x
__device__ float g_QKV [(size_t)ROWS * QKVSTR];   // fused projections
__device__ float g_VT  [(size_t)ROWS * KVDIM];    // V transposed: [b][kvh][d][t]
__device__ float g_O   [(size_t)ROWS * DMODEL];   // flash output, tf32-rounded
__device__ float g_wT  [(size_t)QKVSTR * GK];     // fused [wq;wk;wv] [N,K] K-major, rounded
__device__ float g_woT [(size_t)DMODEL * GK];
__device__ float g_invf[64];

// ---------------- PTX helpers (baseline sm_80+ only) ----------------
__device__ __forceinline__ uint32_t smem_u32(const void* p) {
    uint32_t a;
    asm("{ .reg .u64 t; cvta.to.shared.u64 t, %1; cvt.u32.u64 %0, t; }" : "=r"(a) : "l"(p));
    return a;
}
__device__ __forceinline__ uint32_t f2tf32(float x) {
    uint32_t r; asm("cvt.rna.tf32.f32 %0, %1;" : "=r"(r) : "f"(x)); return r;
}
__device__ __forceinline__ uint32_t swz(uint32_t off) {   // SW128: bits[6:4] ^= bits[9:7]
    return off ^ ((off >> 3) & 0x70);
}
__device__ __forceinline__ void cp16(uint32_t dst, const void* src) {
    asm volatile("cp.async.cg.shared.global [%0], [%1], 16;" :: "r"(dst), "l"(src) : "memory");
}
#define CP_COMMIT() asm volatile("cp.async.commit_group;" ::: "memory")
#define CP_WAIT(n)  asm volatile("cp.async.wait_group %0;" :: "n"(n) : "memory")

__device__ __forceinline__ void ldsm_x4(uint32_t* r, uint32_t addr) {
    asm volatile("ldmatrix.sync.aligned.m8n8.x4.shared.b16 {%0,%1,%2,%3}, [%4];"
                 : "=r"(r[0]), "=r"(r[1]), "=r"(r[2]), "=r"(r[3]) : "r"(addr));
}
__device__ __forceinline__ void mma_tf32(float* d, const uint32_t* a, const uint32_t* b) {
    asm volatile(
        "mma.sync.aligned.m16n8k8.row.col.f32.tf32.tf32.f32 "
        "{%0,%1,%2,%3}, {%4,%5,%6,%7}, {%8,%9}, {%0,%1,%2,%3};"
        : "+f"(d[0]), "+f"(d[1]), "+f"(d[2]), "+f"(d[3])
        : "r"(a[0]), "r"(a[1]), "r"(a[2]), "r"(a[3]), "r"(b[0]), "r"(b[1]));
}
#define STS128(r0, r1, r2, r3, smem_addr) \
    asm volatile("st.shared.v4.b32 [%0], {%1, %2, %3, %4};" \
        :: "r"(smem_addr), "r"(r0), "r"(r1), "r"(r2), "r"(r3) : "memory")
__device__ __forceinline__ void sts64(uint32_t addr, uint32_t a, uint32_t b) {
    asm volatile("st.shared.v2.b32 [%0], {%1,%2};" :: "r"(addr), "r"(a), "r"(b) : "memory");
}

// ---------------- misc small kernels ----------------
__global__ void invf_kernel() {
    int d = threadIdx.x;
    if (d < 64) g_invf[d] = (float)exp(-((double)d / 64.0) * log(10000.0));
}

// All 4 weight transposes in one launch.
__global__ void transpose_all(const float* __restrict__ wq, const float* __restrict__ wk,
                              const float* __restrict__ wv, const float* __restrict__ wo,
                              float* __restrict__ wT, float* __restrict__ woT) {
    __shared__ float t[32][33];
    int bx = blockIdx.x;
    const float* src; float* dst; int N;
    if (bx < 64)       { src = wq; dst = wT;                         N = 2048; }
    else if (bx < 80)  { src = wk; dst = wT + (size_t)2048 * GK;     N = 512;  bx -= 64; }
    else if (bx < 96)  { src = wv; dst = wT + (size_t)2560 * GK;     N = 512;  bx -= 80; }
    else               { src = wo; dst = woT;                        N = 2048; bx -= 96; }
    int n0 = bx * 32, k0 = blockIdx.y * 32;
#pragma unroll
    for (int i = threadIdx.y; i < 32; i += 8)
        t[i][threadIdx.x] = src[(size_t)(k0 + i) * N + n0 + threadIdx.x];
    __syncthreads();
#pragma unroll
    for (int i = threadIdx.y; i < 32; i += 8)
        dst[(size_t)(n0 + i) * GK + k0 + threadIdx.x] = __uint_as_float(f2tf32(t[threadIdx.x][i]));
}

// V transpose: g_QKV V-cols -> g_VT[(b*NKV+kvh)*HD + d][t]
__global__ void vtrans_kernel(const float* __restrict__ QKV, float* __restrict__ VT) {
    __shared__ float t[32][33];
    int bk = blockIdx.z;
    int b = bk >> 2, kvh = bk & 3;
    const float* src = QKV + ((size_t)b * Tn) * QKVSTR + 2560 + kvh * HD;
    float* dst = VT + (size_t)bk * HD * Tn;
    int t0 = blockIdx.x * 32, d0 = blockIdx.y * 32;
#pragma unroll
    for (int i = threadIdx.y; i < 32; i += 8)
        t[i][threadIdx.x] = src[(size_t)(t0 + i) * QKVSTR + d0 + threadIdx.x];
    __syncthreads();
#pragma unroll
    for (int i = threadIdx.y; i < 32; i += 8)
        dst[(size_t)(d0 + i) * Tn + t0 + threadIdx.x] = __uint_as_float(f2tf32(t[threadIdx.x][i]));
}

// elementwise tf32 rounding, vectorized
__global__ void round_rna_vec(const float* __restrict__ in, float* __restrict__ out, int n4) {
    int i = blockIdx.x * blockDim.x + threadIdx.x;
    if (i < n4) {
        float4 v = ((const float4*)in)[i];
        uint4 r = make_uint4(f2tf32(v.x), f2tf32(v.y), f2tf32(v.z), f2tf32(v.w));
        ((uint4*)out)[i] = r;
    }
}

// RoPE on Q and K heads of g_QKV in one launch; outputs tf32-rounded.
#define ROPE_TOTQ (ROWS * NH * 64)
#define ROPE_TOTK (ROWS * NKV * 64)
__global__ void rope_all(float* __restrict__ QKV) {
    int idx = blockIdx.x * blockDim.x + threadIdx.x;
    float* base; int nheads;
    if (idx < ROPE_TOTQ) { base = QKV; nheads = NH; }
    else if (idx < ROPE_TOTQ + ROPE_TOTK) { idx -= ROPE_TOTQ; base = QKV + 2048; nheads = NKV; }
    else return;
    int d    = idx & 63;
    int rest = idx >> 6;
    int hh   = rest % nheads;
    int row  = rest / nheads;
    int t    = row & (Tn - 1);
    float ang = (float)t * g_invf[d];
    float sn, cs;
    sincosf(ang, &sn, &cs);
    float* p = base + (size_t)row * QKVSTR + hh * HD + d;
    float x0 = p[0], x1 = p[64];
    p[0]  = __uint_as_float(f2tf32(x0 * cs - x1 * sn));
    p[64] = __uint_as_float(f2tf32(x1 * cs + x0 * sn));
}

// ---------------- tf32 mma.sync GEMM v4: occupancy 2 ----------------
// C[M,N] = A[M,2048] @ Bt[N,2048]^T.  Block 128x128, BK=32, 3-stage cp.async,
// 8 warps (2x4), warp tile 64x32, 2 CTAs/SM (96KB smem, <=128 regs).
#define BM 128
#define BN 128
#define BK 32
#define NSTG 3
#define ASTG 16384            // 128 rows x 128B
#define BSTG 16384
#define STG  (ASTG + BSTG)
#define GEMM_SMEM (NSTG * STG)   // 98304
#define KITERS (GK / BK)      // 64

__global__ __launch_bounds__(256, 2)
void gemm_mma(const float* __restrict__ A, const float* __restrict__ Bt,
              float* __restrict__ C, int N) {
    extern __shared__ char dsm[];
    const uint32_t base = smem_u32(dsm);

    const int tid  = threadIdx.x;
    const int wid  = tid >> 5;
    const int lane = tid & 31;
    const int mb   = blockIdx.y * BM;
    const int nb   = blockIdx.x * BN;
    const int wm   = (wid & 1) * 64;
    const int wn   = (wid >> 1) * 32;

    const float* Ag = A  + (size_t)mb * GK;
    const float* Bg = Bt + (size_t)nb * GK;

    float acc[4][4][4];
#pragma unroll
    for (int mt = 0; mt < 4; mt++)
#pragma unroll
        for (int nt = 0; nt < 4; nt++)
#pragma unroll
            for (int q = 0; q < 4; q++) acc[mt][nt][q] = 0.f;

    auto issue = [&](int buf, int s) {
        uint32_t sa = base + (uint32_t)buf * STG;
        uint32_t sb = sa + ASTG;
        int k0 = s * BK;
#pragma unroll
        for (int i = 0; i < 4; i++) {
            int cc  = tid + i * 256;
            int row = cc >> 3, kc = cc & 7;
            uint32_t off = swz((uint32_t)(row * 128 + kc * 16));
            cp16(sa + off, Ag + (size_t)row * GK + k0 + kc * 4);
            cp16(sb + off, Bg + (size_t)row * GK + k0 + kc * 4);
        }
        CP_COMMIT();
    };

    issue(0, 0); issue(1, 1);

    const int a_r  = (lane & 7) + ((lane >> 3) & 1) * 8;
    const int a_kc = (lane >> 4);
    const int b_r  = (lane & 7) + (lane >> 4) * 8;
    const int b_kc = ((lane >> 3) & 1);

    int st = 0, stp = 2;
    for (int s = 0; s < KITERS; s++) {
        if (s + 2 < KITERS) CP_WAIT(1); else CP_WAIT(0);
        __syncthreads();
        if (s + 2 < KITERS) issue(stp, s + 2);

        uint32_t sa = base + (uint32_t)st * STG + (uint32_t)(wm * 128);
        uint32_t sb = base + (uint32_t)st * STG + ASTG + (uint32_t)(wn * 128);

#pragma unroll
        for (int ks = 0; ks < 4; ks++) {
            uint32_t afr[4][4];
            uint32_t bfr[4][2];
#pragma unroll
            for (int mt = 0; mt < 4; mt++)
                ldsm_x4(afr[mt], sa + swz((uint32_t)((mt * 16 + a_r) * 128 + (2 * ks + a_kc) * 16)));
            {
                uint32_t tmp[4];
                ldsm_x4(tmp, sb + swz((uint32_t)((b_r) * 128 + (2 * ks + b_kc) * 16)));
                bfr[0][0] = tmp[0]; bfr[0][1] = tmp[1];
                bfr[1][0] = tmp[2]; bfr[1][1] = tmp[3];
                ldsm_x4(tmp, sb + swz((uint32_t)((16 + b_r) * 128 + (2 * ks + b_kc) * 16)));
                bfr[2][0] = tmp[0]; bfr[2][1] = tmp[1];
                bfr[3][0] = tmp[2]; bfr[3][1] = tmp[3];
            }
#pragma unroll
            for (int mt = 0; mt < 4; mt++)
#pragma unroll
                for (int nt = 0; nt < 4; nt++)
                    mma_tf32(acc[mt][nt], afr[mt], bfr[nt]);
        }
        st  = (st  == NSTG - 1) ? 0 : st + 1;
        stp = (stp == NSTG - 1) ? 0 : stp + 1;
    }

    const int g = lane >> 2;
    const int cq = (lane & 3) * 2;
#pragma unroll
    for (int mt = 0; mt < 4; mt++) {
        int row0 = mb + wm + mt * 16 + g;
#pragma unroll
        for (int nt = 0; nt < 4; nt++) {
            int col = nb + wn + nt * 8 + cq;
            *(float2*)(C + (size_t)row0 * N + col)       = make_float2(acc[mt][nt][0], acc[mt][nt][1]);
            *(float2*)(C + (size_t)(row0 + 8) * N + col) = make_float2(acc[mt][nt][2], acc[mt][nt][3]);
        }
    }
}

// ---------------- flash attention on mma.sync tf32 (unchanged core) --------
#define FM 128
#define FN 64
#define FLASH_SMEM 229376

__global__ __launch_bounds__(256, 1)
void flash_mma(const float* __restrict__ QKV, const float* __restrict__ VT,
               float* __restrict__ Og) {
    extern __shared__ float sm[];
    const uint32_t base = smem_u32(sm);
    const int tid = threadIdx.x, wid = tid >> 5, lane = tid & 31;
    const int qb = (Tn / FM - 1) - blockIdx.x;   // heavy blocks first
    const int h = blockIdx.y, b = blockIdx.z;
    const int kvh = h >> 2;
    const int nkt = 2 * qb + 2;

    const float* Qg  = QKV + ((size_t)(b * Tn + qb * FM)) * QKVSTR + h * HD;
    const float* Kg  = QKV + ((size_t)(b * Tn)) * QKVSTR + 2048 + kvh * HD;
    const float* Vtg = VT + ((size_t)(b * NKV + kvh)) * HD * Tn;

    // ---- load Q tile (128 x 128)
#pragma unroll
    for (int i = 0; i < 16; i++) {
        int f = tid + i * 256;
        int qr = f >> 5, dq = f & 31;
        float4 v = *(const float4*)(Qg + (size_t)qr * QKVSTR + dq * 4);
        uint32_t off = swz((uint32_t)(((dq >> 3) * 128 + qr) * 128 + (dq & 7) * 16));
        STS128(__float_as_uint(v.x), __float_as_uint(v.y),
               __float_as_uint(v.z), __float_as_uint(v.w), base + off);
    }

    auto kv_issue = [&](int kt) {
        uint32_t kb = base + 65536u + (uint32_t)(kt & 1) * 65536u;
        uint32_t vb = kb + 32768u;
        const float* Ksrc = Kg  + (size_t)(kt * FN) * QKVSTR;
        const float* Vsrc = Vtg + kt * FN;
#pragma unroll
        for (int i = 0; i < 8; i++) {
            int f = tid + i * 256;
            int kr = f >> 5, dq = f & 31;
            cp16(kb + swz((uint32_t)(((dq >> 3) * 64 + kr) * 128 + (dq & 7) * 16)),
                 Ksrc + (size_t)kr * QKVSTR + dq * 4);
            int d = f >> 4, kq = f & 15;
            cp16(vb + swz((uint32_t)(((kq >> 3) * 128 + d) * 128 + (kq & 7) * 16)),
                 Vsrc + (size_t)d * Tn + kq * 4);
        }
        CP_COMMIT();
    };

    const int a_r  = (lane & 7) + ((lane >> 3) & 1) * 8;
    const int a_kc = lane >> 4;
    const int b_r  = (lane & 7) + (lane >> 4) * 8;
    const int b_kc = (lane >> 3) & 1;
    const int g    = lane >> 2;
    const int cq2  = (lane & 3) * 2;
    const float scale2 = 0.08838834764831843f * 1.4426950408889634f;

    float o[16][4];
#pragma unroll
    for (int nt = 0; nt < 16; nt++)
#pragma unroll
        for (int q = 0; q < 4; q++) o[nt][q] = 0.f;
    float m0 = -1e30f, m1 = -1e30f, l0 = 0.f, l1 = 0.f;

    kv_issue(0);

    for (int kt = 0; kt < nkt; kt++) {
        __syncthreads();
        if (kt + 1 < nkt) { kv_issue(kt + 1); CP_WAIT(1); }
        else              { CP_WAIT(0); }
        __syncthreads();

        uint32_t kb = base + 65536u + (uint32_t)(kt & 1) * 65536u;
        uint32_t vb = kb + 32768u;

        // ---- S = Q @ K^T
        float sacc[8][4];
#pragma unroll
        for (int nt = 0; nt < 8; nt++)
#pragma unroll
            for (int q = 0; q < 4; q++) sacc[nt][q] = 0.f;

#pragma unroll
        for (int ks = 0; ks < 16; ks++) {
            uint32_t af[4];
            ldsm_x4(af, base + swz((uint32_t)((((ks >> 2) * 128 + wid * 16 + a_r) * 128)
                                              + ((ks & 3) * 2 + a_kc) * 16)));
            uint32_t bf[8][2];
#pragma unroll
            for (int np = 0; np < 4; np++) {
                uint32_t tmp[4];
                ldsm_x4(tmp, kb + swz((uint32_t)((((ks >> 2) * 64 + np * 16 + b_r) * 128)
                                                 + ((ks & 3) * 2 + b_kc) * 16)));
                bf[np * 2][0] = tmp[0]; bf[np * 2][1] = tmp[1];
                bf[np * 2 + 1][0] = tmp[2]; bf[np * 2 + 1][1] = tmp[3];
            }
#pragma unroll
            for (int nt = 0; nt < 8; nt++) mma_tf32(sacc[nt], af, bf[nt]);
        }

        // ---- scale + causal mask
        if (kt >= 2 * qb) {
            int rl0 = wid * 16 + g, rl1 = rl0 + 8;
            int kbl = (kt - 2 * qb) * 64;
#pragma unroll
            for (int nt = 0; nt < 8; nt++) {
                int kc0 = kbl + nt * 8 + cq2;
                sacc[nt][0] = (kc0     > rl0) ? -1e30f : sacc[nt][0] * scale2;
                sacc[nt][1] = (kc0 + 1 > rl0) ? -1e30f : sacc[nt][1] * scale2;
                sacc[nt][2] = (kc0     > rl1) ? -1e30f : sacc[nt][2] * scale2;
                sacc[nt][3] = (kc0 + 1 > rl1) ? -1e30f : sacc[nt][3] * scale2;
            }
        } else {
#pragma unroll
            for (int nt = 0; nt < 8; nt++)
#pragma unroll
                for (int q = 0; q < 4; q++) sacc[nt][q] *= scale2;
        }

        // ---- online softmax
        float mx0 = -1e30f, mx1 = -1e30f;
#pragma unroll
        for (int nt = 0; nt < 8; nt++) {
            mx0 = fmaxf(mx0, fmaxf(sacc[nt][0], sacc[nt][1]));
            mx1 = fmaxf(mx1, fmaxf(sacc[nt][2], sacc[nt][3]));
        }
        mx0 = fmaxf(mx0, __shfl_xor_sync(0xffffffffu, mx0, 1));
        mx0 = fmaxf(mx0, __shfl_xor_sync(0xffffffffu, mx0, 2));
        mx1 = fmaxf(mx1, __shfl_xor_sync(0xffffffffu, mx1, 1));
        mx1 = fmaxf(mx1, __shfl_xor_sync(0xffffffffu, mx1, 2));
        float nm0 = fmaxf(m0, mx0), nm1 = fmaxf(m1, mx1);
        float al0 = exp2f(m0 - nm0), al1 = exp2f(m1 - nm1);
        float s0 = 0.f, s1 = 0.f;
#pragma unroll
        for (int nt = 0; nt < 8; nt++) {
            sacc[nt][0] = exp2f(sacc[nt][0] - nm0);
            sacc[nt][1] = exp2f(sacc[nt][1] - nm0);
            sacc[nt][2] = exp2f(sacc[nt][2] - nm1);
            sacc[nt][3] = exp2f(sacc[nt][3] - nm1);
            s0 += sacc[nt][0] + sacc[nt][1];
            s1 += sacc[nt][2] + sacc[nt][3];
        }
        s0 += __shfl_xor_sync(0xffffffffu, s0, 1);
        s0 += __shfl_xor_sync(0xffffffffu, s0, 2);
        s1 += __shfl_xor_sync(0xffffffffu, s1, 1);
        s1 += __shfl_xor_sync(0xffffffffu, s1, 2);
        l0 = l0 * al0 + s0; l1 = l1 * al1 + s1;
        m0 = nm0; m1 = nm1;

#pragma unroll
        for (int nt = 0; nt < 16; nt++) {
            o[nt][0] *= al0; o[nt][1] *= al0;
            o[nt][2] *= al1; o[nt][3] *= al1;
        }

        // ---- store P to smem
        uint32_t pb = base + 196608u;
#pragma unroll
        for (int nt = 0; nt < 8; nt++) {
            int col = nt * 8 + cq2;
            uint32_t o0 = swz((uint32_t)((((col >> 5) * 128 + wid * 16 + g) * 128) + (col & 31) * 4));
            sts64(pb + o0, f2tf32(sacc[nt][0]), f2tf32(sacc[nt][1]));
            uint32_t o1 = swz((uint32_t)((((col >> 5) * 128 + wid * 16 + g + 8) * 128) + (col & 31) * 4));
            sts64(pb + o1, f2tf32(sacc[nt][2]), f2tf32(sacc[nt][3]));
        }
        __syncwarp();

        // ---- O += P @ V
#pragma unroll
        for (int ks = 0; ks < 8; ks++) {
            uint32_t af[4];
            ldsm_x4(af, pb + swz((uint32_t)((((ks >> 2) * 128 + wid * 16 + a_r) * 128)
                                            + ((ks & 3) * 2 + a_kc) * 16)));
#pragma unroll
            for (int np = 0; np < 8; np++) {
                uint32_t tmp[4];
                ldsm_x4(tmp, vb + swz((uint32_t)((((ks >> 2) * 128 + np * 16 + b_r) * 128)
                                                 + ((ks & 3) * 2 + b_kc) * 16)));
                mma_tf32(o[np * 2],     af, tmp);
                mma_tf32(o[np * 2 + 1], af, tmp + 2);
            }
        }
    }

    // ---- epilogue
    float il0 = 1.f / l0, il1 = 1.f / l1;
    float* Ob = Og + ((size_t)(b * Tn + qb * FM + wid * 16)) * DMODEL + h * HD;
#pragma unroll
    for (int nt = 0; nt < 16; nt++) {
        int col = nt * 8 + cq2;
        uint2 w0 = make_uint2(f2tf32(o[nt][0] * il0), f2tf32(o[nt][1] * il0));
        uint2 w1 = make_uint2(f2tf32(o[nt][2] * il1), f2tf32(o[nt][3] * il1));
        *(uint2*)(Ob + (size_t)g * DMODEL + col)       = w0;
        *(uint2*)(Ob + (size_t)(g + 8) * DMODEL + col) = w1;
    }
}

// ---------------- launch ----------------
extern "C" void kernel_launch(void* const* d_in, const int* in_sizes, int n_in,
                              void* d_out, int out_size) {
    (void)in_sizes; (void)n_in; (void)out_size;
    const float* x  = (const float*)d_in[0];
    const float* wq = (const float*)d_in[1];
    const float* wk = (const float*)d_in[2];
    const float* wv = (const float*)d_in[3];
    const float* wo = (const float*)d_in[4];
    float* out = (float*)d_out;

    float *xr, *QKV, *VT, *O, *wT, *woT;
    cudaGetSymbolAddress((void**)&xr,  g_xr);
    cudaGetSymbolAddress((void**)&QKV, g_QKV);
    cudaGetSymbolAddress((void**)&VT,  g_VT);
    cudaGetSymbolAddress((void**)&O,   g_O);
    cudaGetSymbolAddress((void**)&wT,  g_wT);
    cudaGetSymbolAddress((void**)&woT, g_woT);

    cudaFuncSetAttribute(flash_mma, cudaFuncAttributeMaxDynamicSharedMemorySize, FLASH_SMEM);
    cudaFuncSetAttribute(gemm_mma,  cudaFuncAttributeMaxDynamicSharedMemorySize, GEMM_SMEM);

    invf_kernel<<<1, 64>>>();

    // All weight transposes (tf32-rounded, K-major) in one launch
    transpose_all<<<dim3(160, 64), dim3(32, 8)>>>(wq, wk, wv, wo, wT, woT);

    // Activations: tf32 rounding
    {
        int n4 = ROWS * DMODEL / 4;
        round_rna_vec<<<(n4 + 255) / 256, 256>>>(x, xr, n4);
    }

    // Fused QKV projection (one GEMM, N=3072)
    gemm_mma<<<dim3(QKVSTR / BN, ROWS / BM), 256, GEMM_SMEM>>>(xr, wT, QKV, QKVSTR);

    // RoPE on Q and K heads (one launch)
    {
        int tot = ROPE_TOTQ + ROPE_TOTK;
        rope_all<<<(tot + 255) / 256, 256>>>(QKV);
    }

    // V transpose for the PV mma B operand
    vtrans_kernel<<<dim3(Tn / 32, HD / 32, Bn * NKV), dim3(32, 8)>>>(QKV, VT);

    // Causal attention on tensor cores
    flash_mma<<<dim3(Tn / FM, NH, Bn), 256, FLASH_SMEM>>>(QKV, VT, O);

    // Output projection
    gemm_mma<<<dim3(DMODEL / BN, ROWS / BM), 256, GEMM_SMEM>>>(O, woT, out, DMODEL);
}

// round 8
// speedup vs baseline: 1.0121x; 1.0121x over previous
#include <cuda_runtime.h>
#include <math.h>
#include <stdint.h>

// ---------------- problem constants ----------------
#define Bn 2
#define Tn 2048
#define NH 16
#define NKV 4
#define HD 128
#define DMODEL 2048
#define KVDIM 512
#define QKVSTR 3072         // combined QKV row: Q[0:2048) K[2048:2560) V[2560:3072)
#define ROWS 4096           // Bn*Tn
#define GK 2048             // K dim of every GEMM

// ---------------- scratch (__device__ globals) ----------------
__device__ float g_xr  [(size_t)ROWS * DMODEL];   // tf32-rounded x
__device__ float g_QKV [(size_t)ROWS * QKVSTR];   // fused projections
__device__ float g_VT  [(size_t)ROWS * KVDIM];    // V transposed: [b][kvh][d][t]
__device__ float g_O   [(size_t)ROWS * DMODEL];   // flash output, tf32-rounded
__device__ float g_wT  [(size_t)QKVSTR * GK];     // fused [wq;wk;wv] [N,K] K-major, rounded
__device__ float g_woT [(size_t)DMODEL * GK];
__device__ float g_invf[64];

// ---------------- PTX helpers (baseline sm_80+ only) ----------------
__device__ __forceinline__ uint32_t smem_u32(const void* p) {
    uint32_t a;
    asm("{ .reg .u64 t; cvta.to.shared.u64 t, %1; cvt.u32.u64 %0, t; }" : "=r"(a) : "l"(p));
    return a;
}
__device__ __forceinline__ uint32_t f2tf32(float x) {
    uint32_t r; asm("cvt.rna.tf32.f32 %0, %1;" : "=r"(r) : "f"(x)); return r;
}
__device__ __forceinline__ uint32_t swz(uint32_t off) {   // SW128: bits[6:4] ^= bits[9:7]
    return off ^ ((off >> 3) & 0x70);
}
__device__ __forceinline__ void cp16(uint32_t dst, const void* src) {
    asm volatile("cp.async.cg.shared.global [%0], [%1], 16;" :: "r"(dst), "l"(src) : "memory");
}
#define CP_COMMIT() asm volatile("cp.async.commit_group;" ::: "memory")
#define CP_WAIT(n)  asm volatile("cp.async.wait_group %0;" :: "n"(n) : "memory")

__device__ __forceinline__ void ldsm_x4(uint32_t* r, uint32_t addr) {
    asm volatile("ldmatrix.sync.aligned.m8n8.x4.shared.b16 {%0,%1,%2,%3}, [%4];"
                 : "=r"(r[0]), "=r"(r[1]), "=r"(r[2]), "=r"(r[3]) : "r"(addr));
}
__device__ __forceinline__ void mma_tf32(float* d, const uint32_t* a, const uint32_t* b) {
    asm volatile(
        "mma.sync.aligned.m16n8k8.row.col.f32.tf32.tf32.f32 "
        "{%0,%1,%2,%3}, {%4,%5,%6,%7}, {%8,%9}, {%0,%1,%2,%3};"
        : "+f"(d[0]), "+f"(d[1]), "+f"(d[2]), "+f"(d[3])
        : "r"(a[0]), "r"(a[1]), "r"(a[2]), "r"(a[3]), "r"(b[0]), "r"(b[1]));
}
#define STS128(r0, r1, r2, r3, smem_addr) \
    asm volatile("st.shared.v4.b32 [%0], {%1, %2, %3, %4};" \
        :: "r"(smem_addr), "r"(r0), "r"(r1), "r"(r2), "r"(r3) : "memory")
__device__ __forceinline__ void sts64(uint32_t addr, uint32_t a, uint32_t b) {
    asm volatile("st.shared.v2.b32 [%0], {%1,%2};" :: "r"(addr), "r"(a), "r"(b) : "memory");
}

// ---------------- fused prep kernel ----------------
// blocks [0, 10240): weight transposes (160 n-blocks x 64 k-blocks)
// blocks [10240, 18432): x tf32-rounding (8192 blocks x 1024 floats)
// block 18432: invf table
#define TR_BLOCKS 10240
#define RND_BLOCKS 8192
#define PREP_BLOCKS (TR_BLOCKS + RND_BLOCKS + 1)

__global__ void prep_kernel(const float* __restrict__ x,
                            const float* __restrict__ wq, const float* __restrict__ wk,
                            const float* __restrict__ wv, const float* __restrict__ wo,
                            float* __restrict__ xr, float* __restrict__ wT,
                            float* __restrict__ woT) {
    __shared__ float t[32][33];
    int blk = blockIdx.x;
    int tid = threadIdx.x;
    if (blk < TR_BLOCKS) {
        int tx = tid & 31, ty = tid >> 5;
        int bx = blk % 160, kb = blk / 160;
        const float* src; float* dst; int N;
        if (bx < 64)       { src = wq; dst = wT;                     N = 2048; }
        else if (bx < 80)  { src = wk; dst = wT + (size_t)2048 * GK; N = 512;  bx -= 64; }
        else if (bx < 96)  { src = wv; dst = wT + (size_t)2560 * GK; N = 512;  bx -= 80; }
        else               { src = wo; dst = woT;                    N = 2048; bx -= 96; }
        int n0 = bx * 32, k0 = kb * 32;
#pragma unroll
        for (int i = ty; i < 32; i += 8)
            t[i][tx] = src[(size_t)(k0 + i) * N + n0 + tx];
        __syncthreads();
#pragma unroll
        for (int i = ty; i < 32; i += 8)
            dst[(size_t)(n0 + i) * GK + k0 + tx] = __uint_as_float(f2tf32(t[tx][i]));
    } else if (blk < TR_BLOCKS + RND_BLOCKS) {
        int i = (blk - TR_BLOCKS) * 256 + tid;
        float4 v = ((const float4*)x)[i];
        uint4 r = make_uint4(f2tf32(v.x), f2tf32(v.y), f2tf32(v.z), f2tf32(v.w));
        ((uint4*)xr)[i] = r;
    } else {
        if (tid < 64) g_invf[tid] = (float)exp(-((double)tid / 64.0) * log(10000.0));
    }
}

// ---------------- fused rope + V-transpose ----------------
// blocks [0, 20480): rope on Q (first) then K heads
// blocks [20480, 22528): V transpose into g_VT (tf32-rounded)
#define ROPE_TOTQ (ROWS * NH * 64)
#define ROPE_TOTK (ROWS * NKV * 64)
#define ROPE_BLOCKS 20480
#define PQKV_BLOCKS (ROPE_BLOCKS + 2048)

__global__ void postqkv_kernel(float* __restrict__ QKV, float* __restrict__ VT) {
    __shared__ float t[32][33];
    int blk = blockIdx.x;
    int tid = threadIdx.x;
    if (blk < ROPE_BLOCKS) {
        int idx = blk * 256 + tid;
        float* base; int nheads;
        if (idx < ROPE_TOTQ) { base = QKV; nheads = NH; }
        else { idx -= ROPE_TOTQ; base = QKV + 2048; nheads = NKV; }
        int d    = idx & 63;
        int rest = idx >> 6;
        int hh   = rest % nheads;
        int row  = rest / nheads;
        int tt   = row & (Tn - 1);
        float ang = (float)tt * g_invf[d];
        float sn, cs;
        sincosf(ang, &sn, &cs);
        float* p = base + (size_t)row * QKVSTR + hh * HD + d;
        float x0 = p[0], x1 = p[64];
        p[0]  = __uint_as_float(f2tf32(x0 * cs - x1 * sn));
        p[64] = __uint_as_float(f2tf32(x1 * cs + x0 * sn));
    } else {
        int vb = blk - ROPE_BLOCKS;
        int bk = vb >> 8;                 // (b*NKV+kvh)
        int rem = vb & 255;
        int d0 = (rem >> 6) * 32;         // 4 d-blocks
        int t0 = (rem & 63) * 32;         // 64 t-blocks
        int b = bk >> 2, kvh = bk & 3;
        const float* src = QKV + ((size_t)b * Tn) * QKVSTR + 2560 + kvh * HD;
        float* dst = VT + (size_t)bk * HD * Tn;
        int tx = tid & 31, ty = tid >> 5;
#pragma unroll
        for (int i = ty; i < 32; i += 8)
            t[i][tx] = src[(size_t)(t0 + i) * QKVSTR + d0 + tx];
        __syncthreads();
#pragma unroll
        for (int i = ty; i < 32; i += 8)
            dst[(size_t)(d0 + i) * Tn + t0 + tx] = __uint_as_float(f2tf32(t[tx][i]));
    }
}

// ---------------- tf32 mma.sync GEMM (R7 config: occupancy 2) ----------------
#define BM 128
#define BN 128
#define BK 32
#define NSTG 3
#define ASTG 16384
#define BSTG 16384
#define STG  (ASTG + BSTG)
#define GEMM_SMEM (NSTG * STG)   // 98304
#define KITERS (GK / BK)      // 64

__global__ __launch_bounds__(256, 2)
void gemm_mma(const float* __restrict__ A, const float* __restrict__ Bt,
              float* __restrict__ C, int N) {
    extern __shared__ char dsm[];
    const uint32_t base = smem_u32(dsm);

    const int tid  = threadIdx.x;
    const int wid  = tid >> 5;
    const int lane = tid & 31;
    const int mb   = blockIdx.y * BM;
    const int nb   = blockIdx.x * BN;
    const int wm   = (wid & 1) * 64;
    const int wn   = (wid >> 1) * 32;

    const float* Ag = A  + (size_t)mb * GK;
    const float* Bg = Bt + (size_t)nb * GK;

    float acc[4][4][4];
#pragma unroll
    for (int mt = 0; mt < 4; mt++)
#pragma unroll
        for (int nt = 0; nt < 4; nt++)
#pragma unroll
            for (int q = 0; q < 4; q++) acc[mt][nt][q] = 0.f;

    auto issue = [&](int buf, int s) {
        uint32_t sa = base + (uint32_t)buf * STG;
        uint32_t sb = sa + ASTG;
        int k0 = s * BK;
#pragma unroll
        for (int i = 0; i < 4; i++) {
            int cc  = tid + i * 256;
            int row = cc >> 3, kc = cc & 7;
            uint32_t off = swz((uint32_t)(row * 128 + kc * 16));
            cp16(sa + off, Ag + (size_t)row * GK + k0 + kc * 4);
            cp16(sb + off, Bg + (size_t)row * GK + k0 + kc * 4);
        }
        CP_COMMIT();
    };

    issue(0, 0); issue(1, 1);

    const int a_r  = (lane & 7) + ((lane >> 3) & 1) * 8;
    const int a_kc = (lane >> 4);
    const int b_r  = (lane & 7) + (lane >> 4) * 8;
    const int b_kc = ((lane >> 3) & 1);

    int st = 0, stp = 2;
    for (int s = 0; s < KITERS; s++) {
        if (s + 2 < KITERS) CP_WAIT(1); else CP_WAIT(0);
        __syncthreads();
        if (s + 2 < KITERS) issue(stp, s + 2);

        uint32_t sa = base + (uint32_t)st * STG + (uint32_t)(wm * 128);
        uint32_t sb = base + (uint32_t)st * STG + ASTG + (uint32_t)(wn * 128);

#pragma unroll
        for (int ks = 0; ks < 4; ks++) {
            uint32_t afr[4][4];
            uint32_t bfr[4][2];
#pragma unroll
            for (int mt = 0; mt < 4; mt++)
                ldsm_x4(afr[mt], sa + swz((uint32_t)((mt * 16 + a_r) * 128 + (2 * ks + a_kc) * 16)));
            {
                uint32_t tmp[4];
                ldsm_x4(tmp, sb + swz((uint32_t)((b_r) * 128 + (2 * ks + b_kc) * 16)));
                bfr[0][0] = tmp[0]; bfr[0][1] = tmp[1];
                bfr[1][0] = tmp[2]; bfr[1][1] = tmp[3];
                ldsm_x4(tmp, sb + swz((uint32_t)((16 + b_r) * 128 + (2 * ks + b_kc) * 16)));
                bfr[2][0] = tmp[0]; bfr[2][1] = tmp[1];
                bfr[3][0] = tmp[2]; bfr[3][1] = tmp[3];
            }
#pragma unroll
            for (int mt = 0; mt < 4; mt++)
#pragma unroll
                for (int nt = 0; nt < 4; nt++)
                    mma_tf32(acc[mt][nt], afr[mt], bfr[nt]);
        }
        st  = (st  == NSTG - 1) ? 0 : st + 1;
        stp = (stp == NSTG - 1) ? 0 : stp + 1;
    }

    const int g = lane >> 2;
    const int cq = (lane & 3) * 2;
#pragma unroll
    for (int mt = 0; mt < 4; mt++) {
        int row0 = mb + wm + mt * 16 + g;
#pragma unroll
        for (int nt = 0; nt < 4; nt++) {
            int col = nb + wn + nt * 8 + cq;
            *(float2*)(C + (size_t)row0 * N + col)       = make_float2(acc[mt][nt][0], acc[mt][nt][1]);
            *(float2*)(C + (size_t)(row0 + 8) * N + col) = make_float2(acc[mt][nt][2], acc[mt][nt][3]);
        }
    }
}

// ---------------- flash attention: chunked exp/PV overlap ----------------
#define FM 128
#define FN 64
#define FLASH_SMEM 229376

__global__ __launch_bounds__(256, 1)
void flash_mma(const float* __restrict__ QKV, const float* __restrict__ VT,
               float* __restrict__ Og) {
    extern __shared__ float sm[];
    const uint32_t base = smem_u32(sm);
    const int tid = threadIdx.x, wid = tid >> 5, lane = tid & 31;
    const int qb = (Tn / FM - 1) - blockIdx.x;   // heavy blocks first
    const int h = blockIdx.y, b = blockIdx.z;
    const int kvh = h >> 2;
    const int nkt = 2 * qb + 2;

    const float* Qg  = QKV + ((size_t)(b * Tn + qb * FM)) * QKVSTR + h * HD;
    const float* Kg  = QKV + ((size_t)(b * Tn)) * QKVSTR + 2048 + kvh * HD;
    const float* Vtg = VT + ((size_t)(b * NKV + kvh)) * HD * Tn;

    // ---- load Q tile (128 x 128)
#pragma unroll
    for (int i = 0; i < 16; i++) {
        int f = tid + i * 256;
        int qr = f >> 5, dq = f & 31;
        float4 v = *(const float4*)(Qg + (size_t)qr * QKVSTR + dq * 4);
        uint32_t off = swz((uint32_t)(((dq >> 3) * 128 + qr) * 128 + (dq & 7) * 16));
        STS128(__float_as_uint(v.x), __float_as_uint(v.y),
               __float_as_uint(v.z), __float_as_uint(v.w), base + off);
    }

    auto kv_issue = [&](int kt) {
        uint32_t kb = base + 65536u + (uint32_t)(kt & 1) * 65536u;
        uint32_t vb = kb + 32768u;
        const float* Ksrc = Kg  + (size_t)(kt * FN) * QKVSTR;
        const float* Vsrc = Vtg + kt * FN;
#pragma unroll
        for (int i = 0; i < 8; i++) {
            int f = tid + i * 256;
            int kr = f >> 5, dq = f & 31;
            cp16(kb + swz((uint32_t)(((dq >> 3) * 64 + kr) * 128 + (dq & 7) * 16)),
                 Ksrc + (size_t)kr * QKVSTR + dq * 4);
            int d = f >> 4, kq = f & 15;
            cp16(vb + swz((uint32_t)(((kq >> 3) * 128 + d) * 128 + (kq & 7) * 16)),
                 Vsrc + (size_t)d * Tn + kq * 4);
        }
        CP_COMMIT();
    };

    const int a_r  = (lane & 7) + ((lane >> 3) & 1) * 8;
    const int a_kc = lane >> 4;
    const int b_r  = (lane & 7) + (lane >> 4) * 8;
    const int b_kc = (lane >> 3) & 1;
    const int g    = lane >> 2;
    const int cq2  = (lane & 3) * 2;
    const float scale2 = 0.08838834764831843f * 1.4426950408889634f;

    float o[16][4];
#pragma unroll
    for (int nt = 0; nt < 16; nt++)
#pragma unroll
        for (int q = 0; q < 4; q++) o[nt][q] = 0.f;
    // l kept as PER-LANE partials; quad-reduced once in the epilogue.
    float m0 = -1e30f, m1 = -1e30f, l0 = 0.f, l1 = 0.f;

    kv_issue(0);

    for (int kt = 0; kt < nkt; kt++) {
        __syncthreads();
        if (kt + 1 < nkt) { kv_issue(kt + 1); CP_WAIT(1); }
        else              { CP_WAIT(0); }
        __syncthreads();

        uint32_t kb = base + 65536u + (uint32_t)(kt & 1) * 65536u;
        uint32_t vb = kb + 32768u;

        // ---- S = Q @ K^T
        float sacc[8][4];
#pragma unroll
        for (int nt = 0; nt < 8; nt++)
#pragma unroll
            for (int q = 0; q < 4; q++) sacc[nt][q] = 0.f;

#pragma unroll
        for (int ks = 0; ks < 16; ks++) {
            uint32_t af[4];
            ldsm_x4(af, base + swz((uint32_t)((((ks >> 2) * 128 + wid * 16 + a_r) * 128)
                                              + ((ks & 3) * 2 + a_kc) * 16)));
            uint32_t bf[8][2];
#pragma unroll
            for (int np = 0; np < 4; np++) {
                uint32_t tmp[4];
                ldsm_x4(tmp, kb + swz((uint32_t)((((ks >> 2) * 64 + np * 16 + b_r) * 128)
                                                 + ((ks & 3) * 2 + b_kc) * 16)));
                bf[np * 2][0] = tmp[0]; bf[np * 2][1] = tmp[1];
                bf[np * 2 + 1][0] = tmp[2]; bf[np * 2 + 1][1] = tmp[3];
            }
#pragma unroll
            for (int nt = 0; nt < 8; nt++) mma_tf32(sacc[nt], af, bf[nt]);
        }

        // ---- scale + causal mask
        if (kt >= 2 * qb) {
            int rl0 = wid * 16 + g, rl1 = rl0 + 8;
            int kbl = (kt - 2 * qb) * 64;
#pragma unroll
            for (int nt = 0; nt < 8; nt++) {
                int kc0 = kbl + nt * 8 + cq2;
                sacc[nt][0] = (kc0     > rl0) ? -1e30f : sacc[nt][0] * scale2;
                sacc[nt][1] = (kc0 + 1 > rl0) ? -1e30f : sacc[nt][1] * scale2;
                sacc[nt][2] = (kc0     > rl1) ? -1e30f : sacc[nt][2] * scale2;
                sacc[nt][3] = (kc0 + 1 > rl1) ? -1e30f : sacc[nt][3] * scale2;
            }
        } else {
#pragma unroll
            for (int nt = 0; nt < 8; nt++)
#pragma unroll
                for (int q = 0; q < 4; q++) sacc[nt][q] *= scale2;
        }

        // ---- row max (needs all 64 keys) + alpha
        float mx0 = -1e30f, mx1 = -1e30f;
#pragma unroll
        for (int nt = 0; nt < 8; nt++) {
            mx0 = fmaxf(mx0, fmaxf(sacc[nt][0], sacc[nt][1]));
            mx1 = fmaxf(mx1, fmaxf(sacc[nt][2], sacc[nt][3]));
        }
        mx0 = fmaxf(mx0, __shfl_xor_sync(0xffffffffu, mx0, 1));
        mx0 = fmaxf(mx0, __shfl_xor_sync(0xffffffffu, mx0, 2));
        mx1 = fmaxf(mx1, __shfl_xor_sync(0xffffffffu, mx1, 1));
        mx1 = fmaxf(mx1, __shfl_xor_sync(0xffffffffu, mx1, 2));
        float nm0 = fmaxf(m0, mx0), nm1 = fmaxf(m1, mx1);
        float al0 = exp2f(m0 - nm0), al1 = exp2f(m1 - nm1);
        m0 = nm0; m1 = nm1;

        // ---- rescale O accum (fma pipe; overlaps with exp below)
#pragma unroll
        for (int nt = 0; nt < 16; nt++) {
            o[nt][0] *= al0; o[nt][1] *= al0;
            o[nt][2] *= al1; o[nt][3] *= al1;
        }

        uint32_t pb = base + 196608u;
        float s0 = 0.f, s1 = 0.f;

        // ---- chunk 0: exp + store P for keys 0..31 (nt 0..3)
#pragma unroll
        for (int nt = 0; nt < 4; nt++) {
            sacc[nt][0] = exp2f(sacc[nt][0] - nm0);
            sacc[nt][1] = exp2f(sacc[nt][1] - nm0);
            sacc[nt][2] = exp2f(sacc[nt][2] - nm1);
            sacc[nt][3] = exp2f(sacc[nt][3] - nm1);
            s0 += sacc[nt][0] + sacc[nt][1];
            s1 += sacc[nt][2] + sacc[nt][3];
            int col = nt * 8 + cq2;  // < 32
            sts64(pb + swz((uint32_t)(((wid * 16 + g) * 128) + col * 4)),
                  f2tf32(sacc[nt][0]), f2tf32(sacc[nt][1]));
            sts64(pb + swz((uint32_t)(((wid * 16 + g + 8) * 128) + col * 4)),
                  f2tf32(sacc[nt][2]), f2tf32(sacc[nt][3]));
        }
        __syncwarp();

        // ---- chunk 1 exp (MUFU) — interleaves with chunk-0 PV mma (tensor)
#pragma unroll
        for (int nt = 4; nt < 8; nt++) {
            sacc[nt][0] = exp2f(sacc[nt][0] - nm0);
            sacc[nt][1] = exp2f(sacc[nt][1] - nm0);
            sacc[nt][2] = exp2f(sacc[nt][2] - nm1);
            sacc[nt][3] = exp2f(sacc[nt][3] - nm1);
            s0 += sacc[nt][0] + sacc[nt][1];
            s1 += sacc[nt][2] + sacc[nt][3];
        }

        // ---- PV chunk 0: keys 0..31 (ks 0..3)
#pragma unroll
        for (int ks = 0; ks < 4; ks++) {
            uint32_t af[4];
            ldsm_x4(af, pb + swz((uint32_t)(((wid * 16 + a_r) * 128) + (ks * 2 + a_kc) * 16)));
#pragma unroll
            for (int np = 0; np < 8; np++) {
                uint32_t tmp[4];
                ldsm_x4(tmp, vb + swz((uint32_t)(((np * 16 + b_r) * 128) + (ks * 2 + b_kc) * 16)));
                mma_tf32(o[np * 2],     af, tmp);
                mma_tf32(o[np * 2 + 1], af, tmp + 2);
            }
        }

        // ---- store chunk-1 P (keys 32..63 -> P kc block 1)
#pragma unroll
        for (int nt = 4; nt < 8; nt++) {
            int col = nt * 8 + cq2;  // 32..63
            sts64(pb + swz((uint32_t)((128 * 128) + ((wid * 16 + g) * 128) + (col & 31) * 4)),
                  f2tf32(sacc[nt][0]), f2tf32(sacc[nt][1]));
            sts64(pb + swz((uint32_t)((128 * 128) + ((wid * 16 + g + 8) * 128) + (col & 31) * 4)),
                  f2tf32(sacc[nt][2]), f2tf32(sacc[nt][3]));
        }
        __syncwarp();

        // ---- PV chunk 1: keys 32..63 (ks 4..7)
#pragma unroll
        for (int ks = 4; ks < 8; ks++) {
            uint32_t af[4];
            ldsm_x4(af, pb + swz((uint32_t)((128 * 128) + ((wid * 16 + a_r) * 128)
                                            + ((ks - 4) * 2 + a_kc) * 16)));
#pragma unroll
            for (int np = 0; np < 8; np++) {
                uint32_t tmp[4];
                ldsm_x4(tmp, vb + swz((uint32_t)((128 * 128) + ((np * 16 + b_r) * 128)
                                                 + ((ks - 4) * 2 + b_kc) * 16)));
                mma_tf32(o[np * 2],     af, tmp);
                mma_tf32(o[np * 2 + 1], af, tmp + 2);
            }
        }

        // per-lane partial l update (quad-reduced in epilogue)
        l0 = l0 * al0 + s0;
        l1 = l1 * al1 + s1;
    }

    // ---- epilogue: reduce l across the quad, divide, round, store
    l0 += __shfl_xor_sync(0xffffffffu, l0, 1);
    l0 += __shfl_xor_sync(0xffffffffu, l0, 2);
    l1 += __shfl_xor_sync(0xffffffffu, l1, 1);
    l1 += __shfl_xor_sync(0xffffffffu, l1, 2);
    float il0 = 1.f / l0, il1 = 1.f / l1;
    float* Ob = Og + ((size_t)(b * Tn + qb * FM + wid * 16)) * DMODEL + h * HD;
#pragma unroll
    for (int nt = 0; nt < 16; nt++) {
        int col = nt * 8 + cq2;
        uint2 w0 = make_uint2(f2tf32(o[nt][0] * il0), f2tf32(o[nt][1] * il0));
        uint2 w1 = make_uint2(f2tf32(o[nt][2] * il1), f2tf32(o[nt][3] * il1));
        *(uint2*)(Ob + (size_t)g * DMODEL + col)       = w0;
        *(uint2*)(Ob + (size_t)(g + 8) * DMODEL + col) = w1;
    }
}

// ---------------- launch ----------------
extern "C" void kernel_launch(void* const* d_in, const int* in_sizes, int n_in,
                              void* d_out, int out_size) {
    (void)in_sizes; (void)n_in; (void)out_size;
    const float* x  = (const float*)d_in[0];
    const float* wq = (const float*)d_in[1];
    const float* wk = (const float*)d_in[2];
    const float* wv = (const float*)d_in[3];
    const float* wo = (const float*)d_in[4];
    float* out = (float*)d_out;

    float *xr, *QKV, *VT, *O, *wT, *woT;
    cudaGetSymbolAddress((void**)&xr,  g_xr);
    cudaGetSymbolAddress((void**)&QKV, g_QKV);
    cudaGetSymbolAddress((void**)&VT,  g_VT);
    cudaGetSymbolAddress((void**)&O,   g_O);
    cudaGetSymbolAddress((void**)&wT,  g_wT);
    cudaGetSymbolAddress((void**)&woT, g_woT);

    cudaFuncSetAttribute(flash_mma, cudaFuncAttributeMaxDynamicSharedMemorySize, FLASH_SMEM);
    cudaFuncSetAttribute(gemm_mma,  cudaFuncAttributeMaxDynamicSharedMemorySize, GEMM_SMEM);

    // prep: weight transposes + x rounding + invf table (one launch)
    prep_kernel<<<PREP_BLOCKS, 256>>>(x, wq, wk, wv, wo, xr, wT, woT);

    // Fused QKV projection (one GEMM, N=3072)
    gemm_mma<<<dim3(QKVSTR / BN, ROWS / BM), 256, GEMM_SMEM>>>(xr, wT, QKV, QKVSTR);

    // RoPE (Q,K) + V transpose (one launch)
    postqkv_kernel<<<PQKV_BLOCKS, 256>>>(QKV, VT);

    // Causal attention on tensor cores
    flash_mma<<<dim3(Tn / FM, NH, Bn), 256, FLASH_SMEM>>>(QKV, VT, O);

    // Output projection
    gemm_mma<<<dim3(DMODEL / BN, ROWS / BM), 256, GEMM_SMEM>>>(O, woT, out, DMODEL);
}

// round 9
// speedup vs baseline: 1.1366x; 1.1230x over previous
#include <cuda_runtime.h>
#include <cuda_fp16.h>
#include <math.h>
#include <stdint.h>

// ---------------- problem constants ----------------
#define Bn 2
#define Tn 2048
#define NH 16
#define NKV 4
#define HD 128
#define DMODEL 2048
#define KVDIM 512
#define QKVSTR 3072         // combined QKV row: Q[0:2048) K[2048:2560) V[2560:3072)
#define ROWS 4096           // Bn*Tn
#define GK 2048             // K dim of every GEMM

// ---------------- scratch (__device__ globals) ----------------
__device__ float  g_xr  [(size_t)ROWS * DMODEL];  // tf32-rounded x
__device__ float  g_QKV [(size_t)ROWS * QKVSTR];  // fused projections
__device__ __half g_Vh  [(size_t)ROWS * KVDIM];   // V as fp16: [b][kvh][t][d]
__device__ float  g_O   [(size_t)ROWS * DMODEL];  // flash output, tf32-rounded
__device__ float  g_wT  [(size_t)QKVSTR * GK];    // fused [wq;wk;wv] [N,K] K-major, rounded
__device__ float  g_woT [(size_t)DMODEL * GK];
__device__ float  g_invf[64];

// ---------------- PTX helpers (baseline sm_80+ only) ----------------
__device__ __forceinline__ uint32_t smem_u32(const void* p) {
    uint32_t a;
    asm("{ .reg .u64 t; cvta.to.shared.u64 t, %1; cvt.u32.u64 %0, t; }" : "=r"(a) : "l"(p));
    return a;
}
__device__ __forceinline__ uint32_t f2tf32(float x) {
    uint32_t r; asm("cvt.rna.tf32.f32 %0, %1;" : "=r"(r) : "f"(x)); return r;
}
__device__ __forceinline__ uint32_t packh2(float lo, float hi) {   // {lo, hi} packed fp16x2
    uint32_t r; asm("cvt.rn.f16x2.f32 %0, %1, %2;" : "=r"(r) : "f"(hi), "f"(lo)); return r;
}
__device__ __forceinline__ uint32_t swz(uint32_t off) {   // SW128: bits[6:4] ^= bits[9:7]
    return off ^ ((off >> 3) & 0x70);
}
__device__ __forceinline__ void cp16(uint32_t dst, const void* src) {
    asm volatile("cp.async.cg.shared.global [%0], [%1], 16;" :: "r"(dst), "l"(src) : "memory");
}
#define CP_COMMIT() asm volatile("cp.async.commit_group;" ::: "memory")
#define CP_WAIT(n)  asm volatile("cp.async.wait_group %0;" :: "n"(n) : "memory")

__device__ __forceinline__ void ldsm_x4(uint32_t* r, uint32_t addr) {
    asm volatile("ldmatrix.sync.aligned.m8n8.x4.shared.b16 {%0,%1,%2,%3}, [%4];"
                 : "=r"(r[0]), "=r"(r[1]), "=r"(r[2]), "=r"(r[3]) : "r"(addr));
}
__device__ __forceinline__ void ldsm_x4_trans(uint32_t* r, uint32_t addr) {
    asm volatile("ldmatrix.sync.aligned.m8n8.x4.trans.shared.b16 {%0,%1,%2,%3}, [%4];"
                 : "=r"(r[0]), "=r"(r[1]), "=r"(r[2]), "=r"(r[3]) : "r"(addr));
}
__device__ __forceinline__ void mma_tf32(float* d, const uint32_t* a, const uint32_t* b) {
    asm volatile(
        "mma.sync.aligned.m16n8k8.row.col.f32.tf32.tf32.f32 "
        "{%0,%1,%2,%3}, {%4,%5,%6,%7}, {%8,%9}, {%0,%1,%2,%3};"
        : "+f"(d[0]), "+f"(d[1]), "+f"(d[2]), "+f"(d[3])
        : "r"(a[0]), "r"(a[1]), "r"(a[2]), "r"(a[3]), "r"(b[0]), "r"(b[1]));
}
__device__ __forceinline__ void mma_f16(float* d, const uint32_t* a, const uint32_t* b) {
    asm volatile(
        "mma.sync.aligned.m16n8k16.row.col.f32.f16.f16.f32 "
        "{%0,%1,%2,%3}, {%4,%5,%6,%7}, {%8,%9}, {%0,%1,%2,%3};"
        : "+f"(d[0]), "+f"(d[1]), "+f"(d[2]), "+f"(d[3])
        : "r"(a[0]), "r"(a[1]), "r"(a[2]), "r"(a[3]), "r"(b[0]), "r"(b[1]));
}
#define STS128(r0, r1, r2, r3, smem_addr) \
    asm volatile("st.shared.v4.b32 [%0], {%1, %2, %3, %4};" \
        :: "r"(smem_addr), "r"(r0), "r"(r1), "r"(r2), "r"(r3) : "memory")

// ---------------- fused prep kernel ----------------
#define TR_BLOCKS 10240
#define RND_BLOCKS 8192
#define PREP_BLOCKS (TR_BLOCKS + RND_BLOCKS + 1)

__global__ void prep_kernel(const float* __restrict__ x,
                            const float* __restrict__ wq, const float* __restrict__ wk,
                            const float* __restrict__ wv, const float* __restrict__ wo,
                            float* __restrict__ xr, float* __restrict__ wT,
                            float* __restrict__ woT) {
    __shared__ float t[32][33];
    int blk = blockIdx.x;
    int tid = threadIdx.x;
    if (blk < TR_BLOCKS) {
        int tx = tid & 31, ty = tid >> 5;
        int bx = blk % 160, kb = blk / 160;
        const float* src; float* dst; int N;
        if (bx < 64)       { src = wq; dst = wT;                     N = 2048; }
        else if (bx < 80)  { src = wk; dst = wT + (size_t)2048 * GK; N = 512;  bx -= 64; }
        else if (bx < 96)  { src = wv; dst = wT + (size_t)2560 * GK; N = 512;  bx -= 80; }
        else               { src = wo; dst = woT;                    N = 2048; bx -= 96; }
        int n0 = bx * 32, k0 = kb * 32;
#pragma unroll
        for (int i = ty; i < 32; i += 8)
            t[i][tx] = src[(size_t)(k0 + i) * N + n0 + tx];
        __syncthreads();
#pragma unroll
        for (int i = ty; i < 32; i += 8)
            dst[(size_t)(n0 + i) * GK + k0 + tx] = __uint_as_float(f2tf32(t[tx][i]));
    } else if (blk < TR_BLOCKS + RND_BLOCKS) {
        int i = (blk - TR_BLOCKS) * 256 + tid;
        float4 v = ((const float4*)x)[i];
        uint4 r = make_uint4(f2tf32(v.x), f2tf32(v.y), f2tf32(v.z), f2tf32(v.w));
        ((uint4*)xr)[i] = r;
    } else {
        if (tid < 64) g_invf[tid] = (float)exp(-((double)tid / 64.0) * log(10000.0));
    }
}

// ---------------- fused rope + V fp16 conversion ----------------
// blocks [0, 20480): rope on Q then K heads (tf32-rounded outputs)
// blocks [20480, 22528): V -> fp16 copy into g_Vh[b][kvh][t][d]
#define ROPE_TOTQ (ROWS * NH * 64)
#define ROPE_TOTK (ROWS * NKV * 64)
#define ROPE_BLOCKS 20480
#define PQKV_BLOCKS (ROPE_BLOCKS + 2048)

__global__ void postqkv_kernel(float* __restrict__ QKV, __half* __restrict__ Vh) {
    int blk = blockIdx.x;
    int tid = threadIdx.x;
    if (blk < ROPE_BLOCKS) {
        int idx = blk * 256 + tid;
        float* base; int nheads;
        if (idx < ROPE_TOTQ) { base = QKV; nheads = NH; }
        else { idx -= ROPE_TOTQ; base = QKV + 2048; nheads = NKV; }
        int d    = idx & 63;
        int rest = idx >> 6;
        int hh   = rest % nheads;
        int row  = rest / nheads;
        int tt   = row & (Tn - 1);
        float ang = (float)tt * g_invf[d];
        float sn, cs;
        sincosf(ang, &sn, &cs);
        float* p = base + (size_t)row * QKVSTR + hh * HD + d;
        float x0 = p[0], x1 = p[64];
        p[0]  = __uint_as_float(f2tf32(x0 * cs - x1 * sn));
        p[64] = __uint_as_float(f2tf32(x1 * cs + x0 * sn));
    } else {
        int f = (blk - ROPE_BLOCKS) * 256 + tid;   // float4 index, 0..524287
        int row = f >> 7;
        int rem = f & 127;
        int kvh = rem >> 5;
        int dq  = rem & 31;
        float4 v = *(const float4*)(QKV + (size_t)row * QKVSTR + 2560 + kvh * HD + dq * 4);
        __half2 h01 = __floats2half2_rn(v.x, v.y);
        __half2 h23 = __floats2half2_rn(v.z, v.w);
        int b = row >> 11, t = row & (Tn - 1);
        __half* dst = Vh + (((size_t)(b * NKV + kvh) * Tn + t) * HD + dq * 4);
        uint2 u;
        u.x = *(uint32_t*)&h01;
        u.y = *(uint32_t*)&h23;
        *(uint2*)dst = u;
    }
}

// ---------------- tf32 mma.sync GEMM (occupancy 2, unchanged) ----------------
#define BM 128
#define BN 128
#define BK 32
#define NSTG 3
#define ASTG 16384
#define BSTG 16384
#define STG  (ASTG + BSTG)
#define GEMM_SMEM (NSTG * STG)   // 98304
#define KITERS (GK / BK)      // 64

__global__ __launch_bounds__(256, 2)
void gemm_mma(const float* __restrict__ A, const float* __restrict__ Bt,
              float* __restrict__ C, int N) {
    extern __shared__ char dsm[];
    const uint32_t base = smem_u32(dsm);

    const int tid  = threadIdx.x;
    const int wid  = tid >> 5;
    const int lane = tid & 31;
    const int mb   = blockIdx.y * BM;
    const int nb   = blockIdx.x * BN;
    const int wm   = (wid & 1) * 64;
    const int wn   = (wid >> 1) * 32;

    const float* Ag = A  + (size_t)mb * GK;
    const float* Bg = Bt + (size_t)nb * GK;

    float acc[4][4][4];
#pragma unroll
    for (int mt = 0; mt < 4; mt++)
#pragma unroll
        for (int nt = 0; nt < 4; nt++)
#pragma unroll
            for (int q = 0; q < 4; q++) acc[mt][nt][q] = 0.f;

    auto issue = [&](int buf, int s) {
        uint32_t sa = base + (uint32_t)buf * STG;
        uint32_t sb = sa + ASTG;
        int k0 = s * BK;
#pragma unroll
        for (int i = 0; i < 4; i++) {
            int cc  = tid + i * 256;
            int row = cc >> 3, kc = cc & 7;
            uint32_t off = swz((uint32_t)(row * 128 + kc * 16));
            cp16(sa + off, Ag + (size_t)row * GK + k0 + kc * 4);
            cp16(sb + off, Bg + (size_t)row * GK + k0 + kc * 4);
        }
        CP_COMMIT();
    };

    issue(0, 0); issue(1, 1);

    const int a_r  = (lane & 7) + ((lane >> 3) & 1) * 8;
    const int a_kc = (lane >> 4);
    const int b_r  = (lane & 7) + (lane >> 4) * 8;
    const int b_kc = ((lane >> 3) & 1);

    int st = 0, stp = 2;
    for (int s = 0; s < KITERS; s++) {
        if (s + 2 < KITERS) CP_WAIT(1); else CP_WAIT(0);
        __syncthreads();
        if (s + 2 < KITERS) issue(stp, s + 2);

        uint32_t sa = base + (uint32_t)st * STG + (uint32_t)(wm * 128);
        uint32_t sb = base + (uint32_t)st * STG + ASTG + (uint32_t)(wn * 128);

#pragma unroll
        for (int ks = 0; ks < 4; ks++) {
            uint32_t afr[4][4];
            uint32_t bfr[4][2];
#pragma unroll
            for (int mt = 0; mt < 4; mt++)
                ldsm_x4(afr[mt], sa + swz((uint32_t)((mt * 16 + a_r) * 128 + (2 * ks + a_kc) * 16)));
            {
                uint32_t tmp[4];
                ldsm_x4(tmp, sb + swz((uint32_t)((b_r) * 128 + (2 * ks + b_kc) * 16)));
                bfr[0][0] = tmp[0]; bfr[0][1] = tmp[1];
                bfr[1][0] = tmp[2]; bfr[1][1] = tmp[3];
                ldsm_x4(tmp, sb + swz((uint32_t)((16 + b_r) * 128 + (2 * ks + b_kc) * 16)));
                bfr[2][0] = tmp[0]; bfr[2][1] = tmp[1];
                bfr[3][0] = tmp[2]; bfr[3][1] = tmp[3];
            }
#pragma unroll
            for (int mt = 0; mt < 4; mt++)
#pragma unroll
                for (int nt = 0; nt < 4; nt++)
                    mma_tf32(acc[mt][nt], afr[mt], bfr[nt]);
        }
        st  = (st  == NSTG - 1) ? 0 : st + 1;
        stp = (stp == NSTG - 1) ? 0 : stp + 1;
    }

    const int g = lane >> 2;
    const int cq = (lane & 3) * 2;
#pragma unroll
    for (int mt = 0; mt < 4; mt++) {
        int row0 = mb + wm + mt * 16 + g;
#pragma unroll
        for (int nt = 0; nt < 4; nt++) {
            int col = nb + wn + nt * 8 + cq;
            *(float2*)(C + (size_t)row0 * N + col)       = make_float2(acc[mt][nt][0], acc[mt][nt][1]);
            *(float2*)(C + (size_t)(row0 + 8) * N + col) = make_float2(acc[mt][nt][2], acc[mt][nt][3]);
        }
    }
}

// ---------------- flash attention: tf32 S + fp16 PV (register P) ----------
// Smem: Qs 64KB @0; per buffer: K 32KB + V(fp16) 16KB; 2 buffers.
//   K tile:  [dc(4)][key(64)][128B]  (fp32, tf32-rounded)
//   V tile:  [dc(2)][key(64)][128B]  (fp16: 64 d per 128B row-chunk)
#define FM 128
#define FN 64
#define KVBUF 49152
#define FLASH_SMEM (65536 + 2 * KVBUF)   // 163840

__global__ __launch_bounds__(256, 1)
void flash_mma(const float* __restrict__ QKV, const __half* __restrict__ Vh,
               float* __restrict__ Og) {
    extern __shared__ float sm[];
    const uint32_t base = smem_u32(sm);
    const int tid = threadIdx.x, wid = tid >> 5, lane = tid & 31;
    const int qb = (Tn / FM - 1) - blockIdx.x;   // heavy blocks first
    const int h = blockIdx.y, b = blockIdx.z;
    const int kvh = h >> 2;
    const int nkt = 2 * qb + 2;

    const float*  Qg  = QKV + ((size_t)(b * Tn + qb * FM)) * QKVSTR + h * HD;
    const float*  Kg  = QKV + ((size_t)(b * Tn)) * QKVSTR + 2048 + kvh * HD;
    const __half* Vg  = Vh + ((size_t)(b * NKV + kvh)) * Tn * HD;

    // ---- load Q tile (128 x 128)
#pragma unroll
    for (int i = 0; i < 16; i++) {
        int f = tid + i * 256;
        int qr = f >> 5, dq = f & 31;
        float4 v = *(const float4*)(Qg + (size_t)qr * QKVSTR + dq * 4);
        uint32_t off = swz((uint32_t)(((dq >> 3) * 128 + qr) * 128 + (dq & 7) * 16));
        STS128(__float_as_uint(v.x), __float_as_uint(v.y),
               __float_as_uint(v.z), __float_as_uint(v.w), base + off);
    }

    auto kv_issue = [&](int kt) {
        uint32_t kb = base + 65536u + (uint32_t)(kt & 1) * KVBUF;
        uint32_t vb = kb + 32768u;
        const float*  Ksrc = Kg + (size_t)(kt * FN) * QKVSTR;
        const __half* Vsrc = Vg + (size_t)(kt * FN) * HD;
#pragma unroll
        for (int i = 0; i < 8; i++) {          // K: 2048 16B chunks
            int f = tid + i * 256;
            int kr = f >> 5, dq = f & 31;
            cp16(kb + swz((uint32_t)(((dq >> 3) * 64 + kr) * 128 + (dq & 7) * 16)),
                 Ksrc + (size_t)kr * QKVSTR + dq * 4);
        }
#pragma unroll
        for (int i = 0; i < 4; i++) {          // V: 1024 16B chunks (fp16)
            int f = tid + i * 256;
            int key = f >> 4, ch = f & 15;
            cp16(vb + (uint32_t)((ch >> 3) * 8192) + swz((uint32_t)(key * 128 + (ch & 7) * 16)),
                 Vsrc + key * HD + ch * 8);
        }
        CP_COMMIT();
    };

    const int a_r  = (lane & 7) + ((lane >> 3) & 1) * 8;
    const int a_kc = lane >> 4;
    const int b_r  = (lane & 7) + (lane >> 4) * 8;
    const int b_kc = (lane >> 3) & 1;
    const int g    = lane >> 2;
    const int cq2  = (lane & 3) * 2;
    const int vrow = lane & 7;                 // V trans-ldsm row within matrix
    const int vmi  = lane >> 3;                // V matrix index 0..3
    const float scale2 = 0.08838834764831843f * 1.4426950408889634f;

    float o[16][4];
#pragma unroll
    for (int nt = 0; nt < 16; nt++)
#pragma unroll
        for (int q = 0; q < 4; q++) o[nt][q] = 0.f;
    float m0 = -1e30f, m1 = -1e30f, l0 = 0.f, l1 = 0.f;   // l: per-lane partials

    kv_issue(0);

    for (int kt = 0; kt < nkt; kt++) {
        __syncthreads();
        if (kt + 1 < nkt) { kv_issue(kt + 1); CP_WAIT(1); }
        else              { CP_WAIT(0); }
        __syncthreads();

        uint32_t kb = base + 65536u + (uint32_t)(kt & 1) * KVBUF;
        uint32_t vb = kb + 32768u;

        // ---- S = Q @ K^T (tf32)
        float sacc[8][4];
#pragma unroll
        for (int nt = 0; nt < 8; nt++)
#pragma unroll
            for (int q = 0; q < 4; q++) sacc[nt][q] = 0.f;

#pragma unroll
        for (int ks = 0; ks < 16; ks++) {
            uint32_t af[4];
            ldsm_x4(af, base + swz((uint32_t)((((ks >> 2) * 128 + wid * 16 + a_r) * 128)
                                              + ((ks & 3) * 2 + a_kc) * 16)));
            uint32_t bf[8][2];
#pragma unroll
            for (int np = 0; np < 4; np++) {
                uint32_t tmp[4];
                ldsm_x4(tmp, kb + swz((uint32_t)((((ks >> 2) * 64 + np * 16 + b_r) * 128)
                                                 + ((ks & 3) * 2 + b_kc) * 16)));
                bf[np * 2][0] = tmp[0]; bf[np * 2][1] = tmp[1];
                bf[np * 2 + 1][0] = tmp[2]; bf[np * 2 + 1][1] = tmp[3];
            }
#pragma unroll
            for (int nt = 0; nt < 8; nt++) mma_tf32(sacc[nt], af, bf[nt]);
        }

        // ---- scale + causal mask
        if (kt >= 2 * qb) {
            int rl0 = wid * 16 + g, rl1 = rl0 + 8;
            int kbl = (kt - 2 * qb) * 64;
#pragma unroll
            for (int nt = 0; nt < 8; nt++) {
                int kc0 = kbl + nt * 8 + cq2;
                sacc[nt][0] = (kc0     > rl0) ? -1e30f : sacc[nt][0] * scale2;
                sacc[nt][1] = (kc0 + 1 > rl0) ? -1e30f : sacc[nt][1] * scale2;
                sacc[nt][2] = (kc0     > rl1) ? -1e30f : sacc[nt][2] * scale2;
                sacc[nt][3] = (kc0 + 1 > rl1) ? -1e30f : sacc[nt][3] * scale2;
            }
        } else {
#pragma unroll
            for (int nt = 0; nt < 8; nt++)
#pragma unroll
                for (int q = 0; q < 4; q++) sacc[nt][q] *= scale2;
        }

        // ---- row max + alpha
        float mx0 = -1e30f, mx1 = -1e30f;
#pragma unroll
        for (int nt = 0; nt < 8; nt++) {
            mx0 = fmaxf(mx0, fmaxf(sacc[nt][0], sacc[nt][1]));
            mx1 = fmaxf(mx1, fmaxf(sacc[nt][2], sacc[nt][3]));
        }
        mx0 = fmaxf(mx0, __shfl_xor_sync(0xffffffffu, mx0, 1));
        mx0 = fmaxf(mx0, __shfl_xor_sync(0xffffffffu, mx0, 2));
        mx1 = fmaxf(mx1, __shfl_xor_sync(0xffffffffu, mx1, 1));
        mx1 = fmaxf(mx1, __shfl_xor_sync(0xffffffffu, mx1, 2));
        float nm0 = fmaxf(m0, mx0), nm1 = fmaxf(m1, mx1);
        float al0 = exp2f(m0 - nm0), al1 = exp2f(m1 - nm1);
        m0 = nm0; m1 = nm1;

        // ---- rescale O accum
#pragma unroll
        for (int nt = 0; nt < 16; nt++) {
            o[nt][0] *= al0; o[nt][1] *= al0;
            o[nt][2] *= al1; o[nt][3] *= al1;
        }

        // ---- exp (all 64 keys) + per-lane row sums
        float s0 = 0.f, s1 = 0.f;
#pragma unroll
        for (int nt = 0; nt < 8; nt++) {
            sacc[nt][0] = exp2f(sacc[nt][0] - nm0);
            sacc[nt][1] = exp2f(sacc[nt][1] - nm0);
            sacc[nt][2] = exp2f(sacc[nt][2] - nm1);
            sacc[nt][3] = exp2f(sacc[nt][3] - nm1);
            s0 += sacc[nt][0] + sacc[nt][1];
            s1 += sacc[nt][2] + sacc[nt][3];
        }
        l0 = l0 * al0 + s0;
        l1 = l1 * al1 + s1;

        // ---- O += P @ V  (fp16 k16 mma; P packed from registers, no smem)
#pragma unroll
        for (int kc = 0; kc < 4; kc++) {
            uint32_t af[4];
            af[0] = packh2(sacc[2 * kc][0],     sacc[2 * kc][1]);
            af[1] = packh2(sacc[2 * kc][2],     sacc[2 * kc][3]);
            af[2] = packh2(sacc[2 * kc + 1][0], sacc[2 * kc + 1][1]);
            af[3] = packh2(sacc[2 * kc + 1][2], sacc[2 * kc + 1][3]);
            int vkey = kc * 16 + (vmi & 1) * 8 + vrow;
#pragma unroll
            for (int np = 0; np < 16; np += 2) {
                int npp = np + (vmi >> 1);
                uint32_t tmp[4];
                ldsm_x4_trans(tmp, vb + (uint32_t)((npp >> 3) * 8192)
                                      + swz((uint32_t)(vkey * 128 + (npp & 7) * 16)));
                mma_f16(o[np],     af, tmp);
                mma_f16(o[np + 1], af, tmp + 2);
            }
        }
    }

    // ---- epilogue: reduce l across quad, divide, round, store
    l0 += __shfl_xor_sync(0xffffffffu, l0, 1);
    l0 += __shfl_xor_sync(0xffffffffu, l0, 2);
    l1 += __shfl_xor_sync(0xffffffffu, l1, 1);
    l1 += __shfl_xor_sync(0xffffffffu, l1, 2);
    float il0 = 1.f / l0, il1 = 1.f / l1;
    float* Ob = Og + ((size_t)(b * Tn + qb * FM + wid * 16)) * DMODEL + h * HD;
#pragma unroll
    for (int nt = 0; nt < 16; nt++) {
        int col = nt * 8 + cq2;
        uint2 w0 = make_uint2(f2tf32(o[nt][0] * il0), f2tf32(o[nt][1] * il0));
        uint2 w1 = make_uint2(f2tf32(o[nt][2] * il1), f2tf32(o[nt][3] * il1));
        *(uint2*)(Ob + (size_t)g * DMODEL + col)       = w0;
        *(uint2*)(Ob + (size_t)(g + 8) * DMODEL + col) = w1;
    }
}

// ---------------- launch ----------------
extern "C" void kernel_launch(void* const* d_in, const int* in_sizes, int n_in,
                              void* d_out, int out_size) {
    (void)in_sizes; (void)n_in; (void)out_size;
    const float* x  = (const float*)d_in[0];
    const float* wq = (const float*)d_in[1];
    const float* wk = (const float*)d_in[2];
    const float* wv = (const float*)d_in[3];
    const float* wo = (const float*)d_in[4];
    float* out = (float*)d_out;

    float *xr, *QKV, *O, *wT, *woT;
    __half* Vh;
    cudaGetSymbolAddress((void**)&xr,  g_xr);
    cudaGetSymbolAddress((void**)&QKV, g_QKV);
    cudaGetSymbolAddress((void**)&Vh,  g_Vh);
    cudaGetSymbolAddress((void**)&O,   g_O);
    cudaGetSymbolAddress((void**)&wT,  g_wT);
    cudaGetSymbolAddress((void**)&woT, g_woT);

    cudaFuncSetAttribute(flash_mma, cudaFuncAttributeMaxDynamicSharedMemorySize, FLASH_SMEM);
    cudaFuncSetAttribute(gemm_mma,  cudaFuncAttributeMaxDynamicSharedMemorySize, GEMM_SMEM);

    // prep: weight transposes + x rounding + invf table
    prep_kernel<<<PREP_BLOCKS, 256>>>(x, wq, wk, wv, wo, xr, wT, woT);

    // Fused QKV projection
    gemm_mma<<<dim3(QKVSTR / BN, ROWS / BM), 256, GEMM_SMEM>>>(xr, wT, QKV, QKVSTR);

    // RoPE (Q,K) + V fp16 conversion
    postqkv_kernel<<<PQKV_BLOCKS, 256>>>(QKV, Vh);

    // Causal attention
    flash_mma<<<dim3(Tn / FM, NH, Bn), 256, FLASH_SMEM>>>(QKV, Vh, O);

    // Output projection
    gemm_mma<<<dim3(DMODEL / BN, ROWS / BM), 256, GEMM_SMEM>>>(O, woT, out, DMODEL);
}

// round 10
// speedup vs baseline: 1.8794x; 1.6535x over previous
#include <cuda_runtime.h>
#include <cuda_fp16.h>
#include <math.h>
#include <stdint.h>

// ---------------- problem constants ----------------
#define Bn 2
#define Tn 2048
#define NH 16
#define NKV 4
#define HD 128
#define DMODEL 2048
#define KVDIM 512
#define QKVSTR 3072         // combined QKV row: Q[0:2048) K[2048:2560) V[2560:3072)
#define ROWS 4096           // Bn*Tn
#define GK 2048             // K dim of every GEMM

// ---------------- scratch (__device__ globals) ----------------
__device__ __half g_xh  [(size_t)ROWS * DMODEL];  // fp16 x
__device__ float  g_QKV [(size_t)ROWS * QKVSTR];  // fused projections (fp32)
__device__ __half g_QKVh[(size_t)ROWS * QKVSTR];  // fp16 Q(roped), K(roped); V region unused
__device__ __half g_Vh  [(size_t)ROWS * KVDIM];   // V fp16: [b][kvh][t][d]
__device__ __half g_Oh  [(size_t)ROWS * DMODEL];  // flash output fp16
__device__ __half g_wTh [(size_t)QKVSTR * GK];    // fused [wq;wk;wv] [N,K] K-major fp16
__device__ __half g_woTh[(size_t)DMODEL * GK];
__device__ float  g_invf[64];

// ---------------- PTX helpers (baseline sm_80+ only) ----------------
__device__ __forceinline__ uint32_t smem_u32(const void* p) {
    uint32_t a;
    asm("{ .reg .u64 t; cvta.to.shared.u64 t, %1; cvt.u32.u64 %0, t; }" : "=r"(a) : "l"(p));
    return a;
}
__device__ __forceinline__ uint32_t packh2(float lo, float hi) {   // {lo,hi} fp16x2 (lo = low half)
    uint32_t r; asm("cvt.rn.f16x2.f32 %0, %1, %2;" : "=r"(r) : "f"(hi), "f"(lo)); return r;
}
__device__ __forceinline__ uint32_t swz(uint32_t off) {   // SW128: bits[6:4] ^= bits[9:7]
    return off ^ ((off >> 3) & 0x70);
}
__device__ __forceinline__ void cp16(uint32_t dst, const void* src) {
    asm volatile("cp.async.cg.shared.global [%0], [%1], 16;" :: "r"(dst), "l"(src) : "memory");
}
#define CP_COMMIT() asm volatile("cp.async.commit_group;" ::: "memory")
#define CP_WAIT(n)  asm volatile("cp.async.wait_group %0;" :: "n"(n) : "memory")

__device__ __forceinline__ void ldsm_x4(uint32_t* r, uint32_t addr) {
    asm volatile("ldmatrix.sync.aligned.m8n8.x4.shared.b16 {%0,%1,%2,%3}, [%4];"
                 : "=r"(r[0]), "=r"(r[1]), "=r"(r[2]), "=r"(r[3]) : "r"(addr));
}
__device__ __forceinline__ void ldsm_x4_trans(uint32_t* r, uint32_t addr) {
    asm volatile("ldmatrix.sync.aligned.m8n8.x4.trans.shared.b16 {%0,%1,%2,%3}, [%4];"
                 : "=r"(r[0]), "=r"(r[1]), "=r"(r[2]), "=r"(r[3]) : "r"(addr));
}
__device__ __forceinline__ void mma_f16(float* d, const uint32_t* a, const uint32_t* b) {
    asm volatile(
        "mma.sync.aligned.m16n8k16.row.col.f32.f16.f16.f32 "
        "{%0,%1,%2,%3}, {%4,%5,%6,%7}, {%8,%9}, {%0,%1,%2,%3};"
        : "+f"(d[0]), "+f"(d[1]), "+f"(d[2]), "+f"(d[3])
        : "r"(a[0]), "r"(a[1]), "r"(a[2]), "r"(a[3]), "r"(b[0]), "r"(b[1]));
}

// ---------------- fused prep kernel ----------------
// blocks [0, 10240): weight transposes -> fp16 K-major
// blocks [10240, 18432): x -> fp16
// block 18432: invf table
#define TR_BLOCKS 10240
#define RND_BLOCKS 8192
#define PREP_BLOCKS (TR_BLOCKS + RND_BLOCKS + 1)

__global__ void prep_kernel(const float* __restrict__ x,
                            const float* __restrict__ wq, const float* __restrict__ wk,
                            const float* __restrict__ wv, const float* __restrict__ wo,
                            __half* __restrict__ xh, __half* __restrict__ wTh,
                            __half* __restrict__ woTh) {
    __shared__ float t[32][33];
    int blk = blockIdx.x;
    int tid = threadIdx.x;
    if (blk < TR_BLOCKS) {
        int tx = tid & 31, ty = tid >> 5;
        int bx = blk % 160, kb = blk / 160;
        const float* src; __half* dst; int N;
        if (bx < 64)       { src = wq; dst = wTh;                     N = 2048; }
        else if (bx < 80)  { src = wk; dst = wTh + (size_t)2048 * GK; N = 512;  bx -= 64; }
        else if (bx < 96)  { src = wv; dst = wTh + (size_t)2560 * GK; N = 512;  bx -= 80; }
        else               { src = wo; dst = woTh;                    N = 2048; bx -= 96; }
        int n0 = bx * 32, k0 = kb * 32;
#pragma unroll
        for (int i = ty; i < 32; i += 8)
            t[i][tx] = src[(size_t)(k0 + i) * N + n0 + tx];
        __syncthreads();
#pragma unroll
        for (int i = ty; i < 32; i += 8)
            dst[(size_t)(n0 + i) * GK + k0 + tx] = __float2half_rn(t[tx][i]);
    } else if (blk < TR_BLOCKS + RND_BLOCKS) {
        int i = (blk - TR_BLOCKS) * 256 + tid;     // float4 index
        float4 v = ((const float4*)x)[i];
        uint2 u;
        u.x = packh2(v.x, v.y);
        u.y = packh2(v.z, v.w);
        ((uint2*)xh)[i] = u;
    } else {
        if (tid < 64) g_invf[tid] = (float)exp(-((double)tid / 64.0) * log(10000.0));
    }
}

// ---------------- fused rope(fp32->fp16) + V fp16 conversion ----------------
#define ROPE_TOTQ (ROWS * NH * 64)
#define ROPE_TOTK (ROWS * NKV * 64)
#define ROPE_BLOCKS 20480
#define PQKV_BLOCKS (ROPE_BLOCKS + 2048)

__global__ void postqkv_kernel(const float* __restrict__ QKV, __half* __restrict__ QKVh,
                               __half* __restrict__ Vh) {
    int blk = blockIdx.x;
    int tid = threadIdx.x;
    if (blk < ROPE_BLOCKS) {
        int idx = blk * 256 + tid;
        int off; int nheads;
        if (idx < ROPE_TOTQ) { off = 0; nheads = NH; }
        else { idx -= ROPE_TOTQ; off = 2048; nheads = NKV; }
        int d    = idx & 63;
        int rest = idx >> 6;
        int hh   = rest % nheads;
        int row  = rest / nheads;
        int tt   = row & (Tn - 1);
        float ang = (float)tt * g_invf[d];
        float sn, cs;
        sincosf(ang, &sn, &cs);
        const float* p = QKV + (size_t)row * QKVSTR + off + hh * HD + d;
        float x0 = p[0], x1 = p[64];
        __half* q = QKVh + (size_t)row * QKVSTR + off + hh * HD + d;
        q[0]  = __float2half_rn(x0 * cs - x1 * sn);
        q[64] = __float2half_rn(x1 * cs + x0 * sn);
    } else {
        int f = (blk - ROPE_BLOCKS) * 256 + tid;   // float4 index over V region
        int row = f >> 7;
        int rem = f & 127;
        int kvh = rem >> 5;
        int dq  = rem & 31;
        float4 v = *(const float4*)(QKV + (size_t)row * QKVSTR + 2560 + kvh * HD + dq * 4);
        int b = row >> 11, t = row & (Tn - 1);
        __half* dst = Vh + (((size_t)(b * NKV + kvh) * Tn + t) * HD + dq * 4);
        uint2 u;
        u.x = packh2(v.x, v.y);
        u.y = packh2(v.z, v.w);
        *(uint2*)dst = u;
    }
}

// ---------------- fp16 mma.sync GEMM (occupancy 2) ----------------
// C[M,N] = A[M,2048] @ Bt[N,2048]^T, fp16 in / fp32 out.
// Block 128x128, BK=64 halves (128B rows), 3-stage cp.async, 8 warps (2x4),
// warp tile 64x32, m16n8k16.
#define BM 128
#define BN 128
#define NSTG 3
#define ASTG 16384            // 128 rows x 128B
#define BSTG 16384
#define STG  (ASTG + BSTG)
#define GEMM_SMEM (NSTG * STG)   // 98304
#define KITERS 32             // 2048 / 64

__global__ __launch_bounds__(256, 2)
void gemm_mma(const __half* __restrict__ A, const __half* __restrict__ Bt,
              float* __restrict__ C, int N) {
    extern __shared__ char dsm[];
    const uint32_t base = smem_u32(dsm);

    const int tid  = threadIdx.x;
    const int wid  = tid >> 5;
    const int lane = tid & 31;
    const int mb   = blockIdx.y * BM;
    const int nb   = blockIdx.x * BN;
    const int wm   = (wid & 1) * 64;
    const int wn   = (wid >> 1) * 32;

    const __half* Ag = A  + (size_t)mb * GK;
    const __half* Bg = Bt + (size_t)nb * GK;

    float acc[4][4][4];
#pragma unroll
    for (int mt = 0; mt < 4; mt++)
#pragma unroll
        for (int nt = 0; nt < 4; nt++)
#pragma unroll
            for (int q = 0; q < 4; q++) acc[mt][nt][q] = 0.f;

    // 16B chunks: 8 per 128B row; A 1024 chunks + B 1024 chunks per stage.
    auto issue = [&](int buf, int s) {
        uint32_t sa = base + (uint32_t)buf * STG;
        uint32_t sb = sa + ASTG;
        int k0 = s * 64;                 // halves
#pragma unroll
        for (int i = 0; i < 4; i++) {
            int cc  = tid + i * 256;
            int row = cc >> 3, ch = cc & 7;
            uint32_t off = swz((uint32_t)(row * 128 + ch * 16));
            cp16(sa + off, Ag + (size_t)row * GK + k0 + ch * 8);
            cp16(sb + off, Bg + (size_t)row * GK + k0 + ch * 8);
        }
        CP_COMMIT();
    };

    issue(0, 0); issue(1, 1);

    const int a_r  = (lane & 7) + ((lane >> 3) & 1) * 8;
    const int a_kc = (lane >> 4);
    const int b_r  = (lane & 7) + (lane >> 4) * 8;
    const int b_kc = ((lane >> 3) & 1);

    int st = 0, stp = 2;
    for (int s = 0; s < KITERS; s++) {
        if (s + 2 < KITERS) CP_WAIT(1); else CP_WAIT(0);
        __syncthreads();
        if (s + 2 < KITERS) issue(stp, s + 2);

        uint32_t sa = base + (uint32_t)st * STG + (uint32_t)(wm * 128);
        uint32_t sb = base + (uint32_t)st * STG + ASTG + (uint32_t)(wn * 128);

#pragma unroll
        for (int ks = 0; ks < 4; ks++) {       // 4 x k16 per BK=64
            uint32_t afr[4][4];
            uint32_t bfr[4][2];
#pragma unroll
            for (int mt = 0; mt < 4; mt++)
                ldsm_x4(afr[mt], sa + swz((uint32_t)((mt * 16 + a_r) * 128 + (2 * ks + a_kc) * 16)));
            {
                uint32_t tmp[4];
                ldsm_x4(tmp, sb + swz((uint32_t)((b_r) * 128 + (2 * ks + b_kc) * 16)));
                bfr[0][0] = tmp[0]; bfr[0][1] = tmp[1];
                bfr[1][0] = tmp[2]; bfr[1][1] = tmp[3];
                ldsm_x4(tmp, sb + swz((uint32_t)((16 + b_r) * 128 + (2 * ks + b_kc) * 16)));
                bfr[2][0] = tmp[0]; bfr[2][1] = tmp[1];
                bfr[3][0] = tmp[2]; bfr[3][1] = tmp[3];
            }
#pragma unroll
            for (int mt = 0; mt < 4; mt++)
#pragma unroll
                for (int nt = 0; nt < 4; nt++)
                    mma_f16(acc[mt][nt], afr[mt], bfr[nt]);
        }
        st  = (st  == NSTG - 1) ? 0 : st + 1;
        stp = (stp == NSTG - 1) ? 0 : stp + 1;
    }

    const int g = lane >> 2;
    const int cq = (lane & 3) * 2;
#pragma unroll
    for (int mt = 0; mt < 4; mt++) {
        int row0 = mb + wm + mt * 16 + g;
#pragma unroll
        for (int nt = 0; nt < 4; nt++) {
            int col = nb + wn + nt * 8 + cq;
            *(float2*)(C + (size_t)row0 * N + col)       = make_float2(acc[mt][nt][0], acc[mt][nt][1]);
            *(float2*)(C + (size_t)(row0 + 8) * N + col) = make_float2(acc[mt][nt][2], acc[mt][nt][3]);
        }
    }
}

// ---------------- flash attention: all fp16 operands, fp32 accum ------------
// Smem: Q 32KB @0; per buffer K 16KB + V 16KB; 2 buffers -> 96KB total.
//   Q tile: [dc(2)][qrow(128)][64 halves (128B)]
//   K tile: [dc(2)][key(64)][64 halves]
//   V tile: [dc(2)][key(64)][64 halves]  (d-major within chunks, as R9)
#define FM 128
#define FN 64
#define KVBUF 32768
#define FLASH_SMEM (32768 + 2 * KVBUF)   // 98304

__global__ __launch_bounds__(256, 1)
void flash_mma(const __half* __restrict__ QKVh, const __half* __restrict__ Vh,
               __half* __restrict__ Oh) {
    extern __shared__ float sm[];
    const uint32_t base = smem_u32(sm);
    const int tid = threadIdx.x, wid = tid >> 5, lane = tid & 31;
    const int qb = (Tn / FM - 1) - blockIdx.x;   // heavy blocks first
    const int h = blockIdx.y, b = blockIdx.z;
    const int kvh = h >> 2;
    const int nkt = 2 * qb + 2;

    const __half* Qg = QKVh + ((size_t)(b * Tn + qb * FM)) * QKVSTR + h * HD;
    const __half* Kg = QKVh + ((size_t)(b * Tn)) * QKVSTR + 2048 + kvh * HD;
    const __half* Vg = Vh + ((size_t)(b * NKV + kvh)) * Tn * HD;

    // ---- Q tile via cp.async (2048 chunks; folded into group 0 with kv0)
#pragma unroll
    for (int i = 0; i < 8; i++) {
        int f = tid + i * 256;
        int qr = f >> 4, ch = f & 15;
        cp16(base + swz((uint32_t)(((ch >> 3) * 128 + qr) * 128 + (ch & 7) * 16)),
             Qg + (size_t)qr * QKVSTR + ch * 8);
    }

    auto kv_issue = [&](int kt) {
        uint32_t kb = base + 32768u + (uint32_t)(kt & 1) * KVBUF;
        uint32_t vb = kb + 16384u;
        const __half* Ksrc = Kg + (size_t)(kt * FN) * QKVSTR;
        const __half* Vsrc = Vg + (size_t)(kt * FN) * HD;
#pragma unroll
        for (int i = 0; i < 4; i++) {          // K: 1024 chunks
            int f = tid + i * 256;
            int kr = f >> 4, ch = f & 15;
            cp16(kb + swz((uint32_t)(((ch >> 3) * 64 + kr) * 128 + (ch & 7) * 16)),
                 Ksrc + (size_t)kr * QKVSTR + ch * 8);
        }
#pragma unroll
        for (int i = 0; i < 4; i++) {          // V: 1024 chunks
            int f = tid + i * 256;
            int key = f >> 4, ch = f & 15;
            cp16(vb + (uint32_t)((ch >> 3) * 8192) + swz((uint32_t)(key * 128 + (ch & 7) * 16)),
                 Vsrc + key * HD + ch * 8);
        }
        CP_COMMIT();
    };

    const int a_r  = (lane & 7) + ((lane >> 3) & 1) * 8;
    const int a_kc = lane >> 4;
    const int b_r  = (lane & 7) + (lane >> 4) * 8;
    const int b_kc = (lane >> 3) & 1;
    const int g    = lane >> 2;
    const int cq2  = (lane & 3) * 2;
    const int vrow = lane & 7;
    const int vmi  = lane >> 3;
    const float scale2 = 0.08838834764831843f * 1.4426950408889634f;

    float o[16][4];
#pragma unroll
    for (int nt = 0; nt < 16; nt++)
#pragma unroll
        for (int q = 0; q < 4; q++) o[nt][q] = 0.f;
    float m0 = -1e30f, m1 = -1e30f, l0 = 0.f, l1 = 0.f;   // l: per-lane partials

    kv_issue(0);   // commits Q + kv0 as group 0

    for (int kt = 0; kt < nkt; kt++) {
        __syncthreads();
        if (kt + 1 < nkt) { kv_issue(kt + 1); CP_WAIT(1); }
        else              { CP_WAIT(0); }
        __syncthreads();

        uint32_t kb = base + 32768u + (uint32_t)(kt & 1) * KVBUF;
        uint32_t vb = kb + 16384u;

        // ---- S = Q @ K^T (fp16, 8 x k16)
        float sacc[8][4];
#pragma unroll
        for (int nt = 0; nt < 8; nt++)
#pragma unroll
            for (int q = 0; q < 4; q++) sacc[nt][q] = 0.f;

#pragma unroll
        for (int ks = 0; ks < 8; ks++) {
            uint32_t af[4];
            ldsm_x4(af, base + swz((uint32_t)((((ks >> 2) * 128 + wid * 16 + a_r) * 128)
                                              + (((ks & 3) * 2 + a_kc) * 16))));
            uint32_t bf[8][2];
#pragma unroll
            for (int np = 0; np < 4; np++) {
                uint32_t tmp[4];
                ldsm_x4(tmp, kb + swz((uint32_t)((((ks >> 2) * 64 + np * 16 + b_r) * 128)
                                                 + (((ks & 3) * 2 + b_kc) * 16))));
                bf[np * 2][0] = tmp[0]; bf[np * 2][1] = tmp[1];
                bf[np * 2 + 1][0] = tmp[2]; bf[np * 2 + 1][1] = tmp[3];
            }
#pragma unroll
            for (int nt = 0; nt < 8; nt++) mma_f16(sacc[nt], af, bf[nt]);
        }

        // ---- scale + causal mask
        if (kt >= 2 * qb) {
            int rl0 = wid * 16 + g, rl1 = rl0 + 8;
            int kbl = (kt - 2 * qb) * 64;
#pragma unroll
            for (int nt = 0; nt < 8; nt++) {
                int kc0 = kbl + nt * 8 + cq2;
                sacc[nt][0] = (kc0     > rl0) ? -1e30f : sacc[nt][0] * scale2;
                sacc[nt][1] = (kc0 + 1 > rl0) ? -1e30f : sacc[nt][1] * scale2;
                sacc[nt][2] = (kc0     > rl1) ? -1e30f : sacc[nt][2] * scale2;
                sacc[nt][3] = (kc0 + 1 > rl1) ? -1e30f : sacc[nt][3] * scale2;
            }
        } else {
#pragma unroll
            for (int nt = 0; nt < 8; nt++)
#pragma unroll
                for (int q = 0; q < 4; q++) sacc[nt][q] *= scale2;
        }

        // ---- row max + alpha
        float mx0 = -1e30f, mx1 = -1e30f;
#pragma unroll
        for (int nt = 0; nt < 8; nt++) {
            mx0 = fmaxf(mx0, fmaxf(sacc[nt][0], sacc[nt][1]));
            mx1 = fmaxf(mx1, fmaxf(sacc[nt][2], sacc[nt][3]));
        }
        mx0 = fmaxf(mx0, __shfl_xor_sync(0xffffffffu, mx0, 1));
        mx0 = fmaxf(mx0, __shfl_xor_sync(0xffffffffu, mx0, 2));
        mx1 = fmaxf(mx1, __shfl_xor_sync(0xffffffffu, mx1, 1));
        mx1 = fmaxf(mx1, __shfl_xor_sync(0xffffffffu, mx1, 2));
        float nm0 = fmaxf(m0, mx0), nm1 = fmaxf(m1, mx1);
        float al0 = exp2f(m0 - nm0), al1 = exp2f(m1 - nm1);
        m0 = nm0; m1 = nm1;

        // ---- rescale O accum
#pragma unroll
        for (int nt = 0; nt < 16; nt++) {
            o[nt][0] *= al0; o[nt][1] *= al0;
            o[nt][2] *= al1; o[nt][3] *= al1;
        }

        // ---- exp + per-lane row sums
        float s0 = 0.f, s1 = 0.f;
#pragma unroll
        for (int nt = 0; nt < 8; nt++) {
            sacc[nt][0] = exp2f(sacc[nt][0] - nm0);
            sacc[nt][1] = exp2f(sacc[nt][1] - nm0);
            sacc[nt][2] = exp2f(sacc[nt][2] - nm1);
            sacc[nt][3] = exp2f(sacc[nt][3] - nm1);
            s0 += sacc[nt][0] + sacc[nt][1];
            s1 += sacc[nt][2] + sacc[nt][3];
        }
        l0 = l0 * al0 + s0;
        l1 = l1 * al1 + s1;

        // ---- O += P @ V (fp16 k16 mma; P packed from registers)
#pragma unroll
        for (int kc = 0; kc < 4; kc++) {
            uint32_t af[4];
            af[0] = packh2(sacc[2 * kc][0],     sacc[2 * kc][1]);
            af[1] = packh2(sacc[2 * kc][2],     sacc[2 * kc][3]);
            af[2] = packh2(sacc[2 * kc + 1][0], sacc[2 * kc + 1][1]);
            af[3] = packh2(sacc[2 * kc + 1][2], sacc[2 * kc + 1][3]);
            int vkey = kc * 16 + (vmi & 1) * 8 + vrow;
#pragma unroll
            for (int np = 0; np < 16; np += 2) {
                int npp = np + (vmi >> 1);
                uint32_t tmp[4];
                ldsm_x4_trans(tmp, vb + (uint32_t)((npp >> 3) * 8192)
                                      + swz((uint32_t)(vkey * 128 + (npp & 7) * 16)));
                mma_f16(o[np],     af, tmp);
                mma_f16(o[np + 1], af, tmp + 2);
            }
        }
    }

    // ---- epilogue: reduce l, divide, pack fp16, store
    l0 += __shfl_xor_sync(0xffffffffu, l0, 1);
    l0 += __shfl_xor_sync(0xffffffffu, l0, 2);
    l1 += __shfl_xor_sync(0xffffffffu, l1, 1);
    l1 += __shfl_xor_sync(0xffffffffu, l1, 2);
    float il0 = 1.f / l0, il1 = 1.f / l1;
    __half* Ob = Oh + ((size_t)(b * Tn + qb * FM + wid * 16)) * DMODEL + h * HD;
#pragma unroll
    for (int nt = 0; nt < 16; nt++) {
        int col = nt * 8 + cq2;
        uint32_t w0 = packh2(o[nt][0] * il0, o[nt][1] * il0);
        uint32_t w1 = packh2(o[nt][2] * il1, o[nt][3] * il1);
        *(uint32_t*)(Ob + (size_t)g * DMODEL + col)       = w0;
        *(uint32_t*)(Ob + (size_t)(g + 8) * DMODEL + col) = w1;
    }
}

// ---------------- launch ----------------
extern "C" void kernel_launch(void* const* d_in, const int* in_sizes, int n_in,
                              void* d_out, int out_size) {
    (void)in_sizes; (void)n_in; (void)out_size;
    const float* x  = (const float*)d_in[0];
    const float* wq = (const float*)d_in[1];
    const float* wk = (const float*)d_in[2];
    const float* wv = (const float*)d_in[3];
    const float* wo = (const float*)d_in[4];
    float* out = (float*)d_out;

    float *QKV;
    __half *xh, *QKVh, *Vh, *Oh, *wTh, *woTh;
    cudaGetSymbolAddress((void**)&xh,   g_xh);
    cudaGetSymbolAddress((void**)&QKV,  g_QKV);
    cudaGetSymbolAddress((void**)&QKVh, g_QKVh);
    cudaGetSymbolAddress((void**)&Vh,   g_Vh);
    cudaGetSymbolAddress((void**)&Oh,   g_Oh);
    cudaGetSymbolAddress((void**)&wTh,  g_wTh);
    cudaGetSymbolAddress((void**)&woTh, g_woTh);

    cudaFuncSetAttribute(flash_mma, cudaFuncAttributeMaxDynamicSharedMemorySize, FLASH_SMEM);
    cudaFuncSetAttribute(gemm_mma,  cudaFuncAttributeMaxDynamicSharedMemorySize, GEMM_SMEM);

    // prep: weight transposes (fp16 K-major) + x fp16 + invf
    prep_kernel<<<PREP_BLOCKS, 256>>>(x, wq, wk, wv, wo, xh, wTh, woTh);

    // Fused QKV projection (fp16 in, fp32 out)
    gemm_mma<<<dim3(QKVSTR / BN, ROWS / BM), 256, GEMM_SMEM>>>(xh, wTh, QKV, QKVSTR);

    // RoPE (Q,K) -> fp16 QKVh; V -> fp16 Vh
    postqkv_kernel<<<PQKV_BLOCKS, 256>>>(QKV, QKVh, Vh);

    // Causal attention (all fp16 operands)
    flash_mma<<<dim3(Tn / FM, NH, Bn), 256, FLASH_SMEM>>>(QKVh, Vh, Oh);

    // Output projection (fp16 in, fp32 out)
    gemm_mma<<<dim3(DMODEL / BN, ROWS / BM), 256, GEMM_SMEM>>>(Oh, woTh, out, DMODEL);
}

// round 11
// speedup vs baseline: 1.9941x; 1.0610x over previous
#include <cuda_runtime.h>
#include <cuda_fp16.h>
#include <math.h>
#include <stdint.h>

// ---------------- problem constants ----------------
#define Bn 2
#define Tn 2048
#define NH 16
#define NKV 4
#define HD 128
#define DMODEL 2048
#define KVDIM 512
#define QKVSTR 3072         // combined QKV row: Q[0:2048) K[2048:2560) V[2560:3072)
#define ROWS 4096           // Bn*Tn
#define GK 2048             // K dim of every GEMM

// ---------------- scratch (__device__ globals) ----------------
__device__ __half g_xh  [(size_t)ROWS * DMODEL];  // fp16 x
__device__ __half g_QKVh[(size_t)ROWS * QKVSTR];  // fp16 Q,K (roped in place); V region unused
__device__ __half g_Vh  [(size_t)ROWS * KVDIM];   // V fp16: [b][kvh][t][d]
__device__ __half g_Oh  [(size_t)ROWS * DMODEL];  // flash output fp16
__device__ __half g_wTh [(size_t)QKVSTR * GK];    // fused [wq;wk;wv] [N,K] K-major fp16
__device__ __half g_woTh[(size_t)DMODEL * GK];
__device__ float  g_invf[64];

// ---------------- PTX helpers (baseline sm_80+ only) ----------------
__device__ __forceinline__ uint32_t smem_u32(const void* p) {
    uint32_t a;
    asm("{ .reg .u64 t; cvta.to.shared.u64 t, %1; cvt.u32.u64 %0, t; }" : "=r"(a) : "l"(p));
    return a;
}
__device__ __forceinline__ uint32_t packh2(float lo, float hi) {   // {lo,hi} fp16x2 (lo = low half)
    uint32_t r; asm("cvt.rn.f16x2.f32 %0, %1, %2;" : "=r"(r) : "f"(hi), "f"(lo)); return r;
}
__device__ __forceinline__ uint32_t swz(uint32_t off) {   // SW128: bits[6:4] ^= bits[9:7]
    return off ^ ((off >> 3) & 0x70);
}
__device__ __forceinline__ void cp16(uint32_t dst, const void* src) {
    asm volatile("cp.async.cg.shared.global [%0], [%1], 16;" :: "r"(dst), "l"(src) : "memory");
}
#define CP_COMMIT() asm volatile("cp.async.commit_group;" ::: "memory")
#define CP_WAIT(n)  asm volatile("cp.async.wait_group %0;" :: "n"(n) : "memory")

__device__ __forceinline__ void ldsm_x4(uint32_t* r, uint32_t addr) {
    asm volatile("ldmatrix.sync.aligned.m8n8.x4.shared.b16 {%0,%1,%2,%3}, [%4];"
                 : "=r"(r[0]), "=r"(r[1]), "=r"(r[2]), "=r"(r[3]) : "r"(addr));
}
__device__ __forceinline__ void ldsm_x4_trans(uint32_t* r, uint32_t addr) {
    asm volatile("ldmatrix.sync.aligned.m8n8.x4.trans.shared.b16 {%0,%1,%2,%3}, [%4];"
                 : "=r"(r[0]), "=r"(r[1]), "=r"(r[2]), "=r"(r[3]) : "r"(addr));
}
__device__ __forceinline__ void mma_f16(float* d, const uint32_t* a, const uint32_t* b) {
    asm volatile(
        "mma.sync.aligned.m16n8k16.row.col.f32.f16.f16.f32 "
        "{%0,%1,%2,%3}, {%4,%5,%6,%7}, {%8,%9}, {%0,%1,%2,%3};"
        : "+f"(d[0]), "+f"(d[1]), "+f"(d[2]), "+f"(d[3])
        : "r"(a[0]), "r"(a[1]), "r"(a[2]), "r"(a[3]), "r"(b[0]), "r"(b[1]));
}

// ---------------- fused prep kernel ----------------
#define TR_BLOCKS 10240
#define RND_BLOCKS 8192
#define PREP_BLOCKS (TR_BLOCKS + RND_BLOCKS + 1)

__global__ void prep_kernel(const float* __restrict__ x,
                            const float* __restrict__ wq, const float* __restrict__ wk,
                            const float* __restrict__ wv, const float* __restrict__ wo,
                            __half* __restrict__ xh, __half* __restrict__ wTh,
                            __half* __restrict__ woTh) {
    __shared__ float t[32][33];
    int blk = blockIdx.x;
    int tid = threadIdx.x;
    if (blk < TR_BLOCKS) {
        int tx = tid & 31, ty = tid >> 5;
        int bx = blk % 160, kb = blk / 160;
        const float* src; __half* dst; int N;
        if (bx < 64)       { src = wq; dst = wTh;                     N = 2048; }
        else if (bx < 80)  { src = wk; dst = wTh + (size_t)2048 * GK; N = 512;  bx -= 64; }
        else if (bx < 96)  { src = wv; dst = wTh + (size_t)2560 * GK; N = 512;  bx -= 80; }
        else               { src = wo; dst = woTh;                    N = 2048; bx -= 96; }
        int n0 = bx * 32, k0 = kb * 32;
#pragma unroll
        for (int i = ty; i < 32; i += 8)
            t[i][tx] = src[(size_t)(k0 + i) * N + n0 + tx];
        __syncthreads();
#pragma unroll
        for (int i = ty; i < 32; i += 8)
            dst[(size_t)(n0 + i) * GK + k0 + tx] = __float2half_rn(t[tx][i]);
    } else if (blk < TR_BLOCKS + RND_BLOCKS) {
        int i = (blk - TR_BLOCKS) * 256 + tid;     // float4 index
        float4 v = ((const float4*)x)[i];
        uint2 u;
        u.x = packh2(v.x, v.y);
        u.y = packh2(v.z, v.w);
        ((uint2*)xh)[i] = u;
    } else {
        if (tid < 64) g_invf[tid] = (float)exp(-((double)tid / 64.0) * log(10000.0));
    }
}

// ---------------- rope (in-place on fp16 QKVh, Q and K regions) -----------
#define ROPE_TOTQ (ROWS * NH * 64)
#define ROPE_TOTK (ROWS * NKV * 64)
#define ROPE_BLOCKS 20480

__global__ void rope_kernel(__half* __restrict__ QKVh) {
    int idx = blockIdx.x * 256 + threadIdx.x;
    int off; int nheads;
    if (idx < ROPE_TOTQ) { off = 0; nheads = NH; }
    else { idx -= ROPE_TOTQ; off = 2048; nheads = NKV; }
    int d    = idx & 63;
    int rest = idx >> 6;
    int hh   = rest % nheads;
    int row  = rest / nheads;
    int tt   = row & (Tn - 1);
    float ang = (float)tt * g_invf[d];
    float sn, cs;
    sincosf(ang, &sn, &cs);
    __half* p = QKVh + (size_t)row * QKVSTR + off + hh * HD + d;
    float x0 = __half2float(p[0]), x1 = __half2float(p[64]);
    p[0]  = __float2half_rn(x0 * cs - x1 * sn);
    p[64] = __float2half_rn(x1 * cs + x0 * sn);
}

// ---------------- fp16 mma.sync GEMM (occupancy 2) ----------------
// C[M,N] = A[M,2048] @ Bt[N,2048]^T, fp16 in.
// MODE 0: fp32 output row-major (Cout = float*).
// MODE 1: fp16 output; cols <2560 -> QKVh row-major; cols >=2560 -> g_Vh
//         scattered to [b][kvh][t][d].
#define BM 128
#define BN 128
#define NSTG 3
#define ASTG 16384
#define BSTG 16384
#define STG  (ASTG + BSTG)
#define GEMM_SMEM (NSTG * STG)   // 98304
#define KITERS 32             // 2048 / 64

template <int MODE>
__global__ __launch_bounds__(256, 2)
void gemm_mma(const __half* __restrict__ A, const __half* __restrict__ Bt,
              void* __restrict__ Cout, int N) {
    extern __shared__ char dsm[];
    const uint32_t base = smem_u32(dsm);

    const int tid  = threadIdx.x;
    const int wid  = tid >> 5;
    const int lane = tid & 31;
    const int mb   = blockIdx.y * BM;
    const int nb   = blockIdx.x * BN;
    const int wm   = (wid & 1) * 64;
    const int wn   = (wid >> 1) * 32;

    const __half* Ag = A  + (size_t)mb * GK;
    const __half* Bg = Bt + (size_t)nb * GK;

    float acc[4][4][4];
#pragma unroll
    for (int mt = 0; mt < 4; mt++)
#pragma unroll
        for (int nt = 0; nt < 4; nt++)
#pragma unroll
            for (int q = 0; q < 4; q++) acc[mt][nt][q] = 0.f;

    auto issue = [&](int buf, int s) {
        uint32_t sa = base + (uint32_t)buf * STG;
        uint32_t sb = sa + ASTG;
        int k0 = s * 64;
#pragma unroll
        for (int i = 0; i < 4; i++) {
            int cc  = tid + i * 256;
            int row = cc >> 3, ch = cc & 7;
            uint32_t off = swz((uint32_t)(row * 128 + ch * 16));
            cp16(sa + off, Ag + (size_t)row * GK + k0 + ch * 8);
            cp16(sb + off, Bg + (size_t)row * GK + k0 + ch * 8);
        }
        CP_COMMIT();
    };

    issue(0, 0); issue(1, 1);

    const int a_r  = (lane & 7) + ((lane >> 3) & 1) * 8;
    const int a_kc = (lane >> 4);
    const int b_r  = (lane & 7) + (lane >> 4) * 8;
    const int b_kc = ((lane >> 3) & 1);

    int st = 0, stp = 2;
    for (int s = 0; s < KITERS; s++) {
        if (s + 2 < KITERS) CP_WAIT(1); else CP_WAIT(0);
        __syncthreads();
        if (s + 2 < KITERS) issue(stp, s + 2);

        uint32_t sa = base + (uint32_t)st * STG + (uint32_t)(wm * 128);
        uint32_t sb = base + (uint32_t)st * STG + ASTG + (uint32_t)(wn * 128);

#pragma unroll
        for (int ks = 0; ks < 4; ks++) {
            uint32_t afr[4][4];
            uint32_t bfr[4][2];
#pragma unroll
            for (int mt = 0; mt < 4; mt++)
                ldsm_x4(afr[mt], sa + swz((uint32_t)((mt * 16 + a_r) * 128 + (2 * ks + a_kc) * 16)));
            {
                uint32_t tmp[4];
                ldsm_x4(tmp, sb + swz((uint32_t)((b_r) * 128 + (2 * ks + b_kc) * 16)));
                bfr[0][0] = tmp[0]; bfr[0][1] = tmp[1];
                bfr[1][0] = tmp[2]; bfr[1][1] = tmp[3];
                ldsm_x4(tmp, sb + swz((uint32_t)((16 + b_r) * 128 + (2 * ks + b_kc) * 16)));
                bfr[2][0] = tmp[0]; bfr[2][1] = tmp[1];
                bfr[3][0] = tmp[2]; bfr[3][1] = tmp[3];
            }
#pragma unroll
            for (int mt = 0; mt < 4; mt++)
#pragma unroll
                for (int nt = 0; nt < 4; nt++)
                    mma_f16(acc[mt][nt], afr[mt], bfr[nt]);
        }
        st  = (st  == NSTG - 1) ? 0 : st + 1;
        stp = (stp == NSTG - 1) ? 0 : stp + 1;
    }

    const int g = lane >> 2;
    const int cq = (lane & 3) * 2;
#pragma unroll
    for (int mt = 0; mt < 4; mt++) {
        int row0 = mb + wm + mt * 16 + g;
#pragma unroll
        for (int nt = 0; nt < 4; nt++) {
            int col = nb + wn + nt * 8 + cq;
            if (MODE == 0) {
                float* C = (float*)Cout;
                *(float2*)(C + (size_t)row0 * N + col)       = make_float2(acc[mt][nt][0], acc[mt][nt][1]);
                *(float2*)(C + (size_t)(row0 + 8) * N + col) = make_float2(acc[mt][nt][2], acc[mt][nt][3]);
            } else {
                uint32_t w0 = packh2(acc[mt][nt][0], acc[mt][nt][1]);
                uint32_t w1 = packh2(acc[mt][nt][2], acc[mt][nt][3]);
                if (col < 2560) {   // Q or K -> QKVh row-major
                    __half* C = (__half*)Cout;
                    *(uint32_t*)(C + (size_t)row0 * QKVSTR + col)       = w0;
                    *(uint32_t*)(C + (size_t)(row0 + 8) * QKVSTR + col) = w1;
                } else {            // V -> g_Vh [b][kvh][t][d]
                    int rel = col - 2560;
                    int kvh = rel >> 7, d = rel & 127;
                    int b0 = row0 >> 11, t0 = row0 & (Tn - 1);
                    int b1 = (row0 + 8) >> 11, t1 = (row0 + 8) & (Tn - 1);
                    *(uint32_t*)(g_Vh + (((size_t)(b0 * NKV + kvh) * Tn + t0) * HD + d)) = w0;
                    *(uint32_t*)(g_Vh + (((size_t)(b1 * NKV + kvh) * Tn + t1) * HD + d)) = w1;
                }
            }
        }
    }
}

// ---------------- flash attention: FM=64, 128 threads, 2 CTAs/SM ----------
// Smem: Q 16KB @0; per buffer K 16KB + V 16KB; 2 buffers -> 80KB total.
//   Q tile: [dc(2)][qrow(64)][64 halves (128B)]   dc stride 8192
//   K tile: [dc(2)][key(64)][64 halves]            dc stride 8192
//   V tile: [kc(2)][key(64)][64 d-halves]          kc stride 8192
#define FM 64
#define FN 64
#define KVBUF 32768
#define FLASH_SMEM (16384 + 2 * KVBUF)   // 81920
#define FTHREADS 128

__global__ __launch_bounds__(FTHREADS, 2)
void flash_mma(const __half* __restrict__ QKVh, const __half* __restrict__ Vh,
               __half* __restrict__ Oh) {
    extern __shared__ float sm[];
    const uint32_t base = smem_u32(sm);
    const int tid = threadIdx.x, wid = tid >> 5, lane = tid & 31;
    const int qb = (Tn / FM - 1) - blockIdx.x;   // heavy blocks first
    const int h = blockIdx.y, b = blockIdx.z;
    const int kvh = h >> 2;
    const int nkt = qb + 1;

    const __half* Qg = QKVh + ((size_t)(b * Tn + qb * FM)) * QKVSTR + h * HD;
    const __half* Kg = QKVh + ((size_t)(b * Tn)) * QKVSTR + 2048 + kvh * HD;
    const __half* Vg = Vh + ((size_t)(b * NKV + kvh)) * Tn * HD;

    // ---- Q tile: 1024 16B chunks
#pragma unroll
    for (int i = 0; i < 8; i++) {
        int f = tid + i * FTHREADS;
        int qr = f >> 4, ch = f & 15;
        cp16(base + (uint32_t)((ch >> 3) * 8192) + swz((uint32_t)(qr * 128 + (ch & 7) * 16)),
             Qg + (size_t)qr * QKVSTR + ch * 8);
    }

    auto kv_issue = [&](int kt) {
        uint32_t kb = base + 16384u + (uint32_t)(kt & 1) * KVBUF;
        uint32_t vb = kb + 16384u;
        const __half* Ksrc = Kg + (size_t)(kt * FN) * QKVSTR;
        const __half* Vsrc = Vg + (size_t)(kt * FN) * HD;
#pragma unroll
        for (int i = 0; i < 8; i++) {          // K: 1024 chunks
            int f = tid + i * FTHREADS;
            int kr = f >> 4, ch = f & 15;
            cp16(kb + (uint32_t)((ch >> 3) * 8192) + swz((uint32_t)(kr * 128 + (ch & 7) * 16)),
                 Ksrc + (size_t)kr * QKVSTR + ch * 8);
        }
#pragma unroll
        for (int i = 0; i < 8; i++) {          // V: 1024 chunks
            int f = tid + i * FTHREADS;
            int key = f >> 4, ch = f & 15;
            cp16(vb + (uint32_t)((ch >> 3) * 8192) + swz((uint32_t)(key * 128 + (ch & 7) * 16)),
                 Vsrc + key * HD + ch * 8);
        }
        CP_COMMIT();
    };

    const int a_r  = (lane & 7) + ((lane >> 3) & 1) * 8;
    const int a_kc = lane >> 4;
    const int b_r  = (lane & 7) + (lane >> 4) * 8;
    const int b_kc = (lane >> 3) & 1;
    const int g    = lane >> 2;
    const int cq2  = (lane & 3) * 2;
    const int vrow = lane & 7;
    const int vmi  = lane >> 3;
    const float scale2 = 0.08838834764831843f * 1.4426950408889634f;

    float o[16][4];
#pragma unroll
    for (int nt = 0; nt < 16; nt++)
#pragma unroll
        for (int q = 0; q < 4; q++) o[nt][q] = 0.f;
    float m0 = -1e30f, m1 = -1e30f, l0 = 0.f, l1 = 0.f;   // l: per-lane partials

    kv_issue(0);   // commits Q + kv0 as group 0

    for (int kt = 0; kt < nkt; kt++) {
        __syncthreads();
        if (kt + 1 < nkt) { kv_issue(kt + 1); CP_WAIT(1); }
        else              { CP_WAIT(0); }
        __syncthreads();

        uint32_t kb = base + 16384u + (uint32_t)(kt & 1) * KVBUF;
        uint32_t vb = kb + 16384u;

        // ---- S = Q @ K^T (fp16, 8 x k16)
        float sacc[8][4];
#pragma unroll
        for (int nt = 0; nt < 8; nt++)
#pragma unroll
            for (int q = 0; q < 4; q++) sacc[nt][q] = 0.f;

#pragma unroll
        for (int ks = 0; ks < 8; ks++) {
            uint32_t af[4];
            ldsm_x4(af, base + (uint32_t)((ks >> 2) * 8192)
                        + swz((uint32_t)((wid * 16 + a_r) * 128 + ((ks & 3) * 2 + a_kc) * 16)));
            uint32_t bf[8][2];
#pragma unroll
            for (int np = 0; np < 4; np++) {
                uint32_t tmp[4];
                ldsm_x4(tmp, kb + (uint32_t)((ks >> 2) * 8192)
                             + swz((uint32_t)((np * 16 + b_r) * 128 + ((ks & 3) * 2 + b_kc) * 16)));
                bf[np * 2][0] = tmp[0]; bf[np * 2][1] = tmp[1];
                bf[np * 2 + 1][0] = tmp[2]; bf[np * 2 + 1][1] = tmp[3];
            }
#pragma unroll
            for (int nt = 0; nt < 8; nt++) mma_f16(sacc[nt], af, bf[nt]);
        }

        // ---- scale + causal mask (diagonal tile only)
        if (kt == qb) {
            int rl0 = wid * 16 + g, rl1 = rl0 + 8;
#pragma unroll
            for (int nt = 0; nt < 8; nt++) {
                int kc0 = nt * 8 + cq2;
                sacc[nt][0] = (kc0     > rl0) ? -1e30f : sacc[nt][0] * scale2;
                sacc[nt][1] = (kc0 + 1 > rl0) ? -1e30f : sacc[nt][1] * scale2;
                sacc[nt][2] = (kc0     > rl1) ? -1e30f : sacc[nt][2] * scale2;
                sacc[nt][3] = (kc0 + 1 > rl1) ? -1e30f : sacc[nt][3] * scale2;
            }
        } else {
#pragma unroll
            for (int nt = 0; nt < 8; nt++)
#pragma unroll
                for (int q = 0; q < 4; q++) sacc[nt][q] *= scale2;
        }

        // ---- row max + alpha
        float mx0 = -1e30f, mx1 = -1e30f;
#pragma unroll
        for (int nt = 0; nt < 8; nt++) {
            mx0 = fmaxf(mx0, fmaxf(sacc[nt][0], sacc[nt][1]));
            mx1 = fmaxf(mx1, fmaxf(sacc[nt][2], sacc[nt][3]));
        }
        mx0 = fmaxf(mx0, __shfl_xor_sync(0xffffffffu, mx0, 1));
        mx0 = fmaxf(mx0, __shfl_xor_sync(0xffffffffu, mx0, 2));
        mx1 = fmaxf(mx1, __shfl_xor_sync(0xffffffffu, mx1, 1));
        mx1 = fmaxf(mx1, __shfl_xor_sync(0xffffffffu, mx1, 2));
        float nm0 = fmaxf(m0, mx0), nm1 = fmaxf(m1, mx1);
        float al0 = exp2f(m0 - nm0), al1 = exp2f(m1 - nm1);
        m0 = nm0; m1 = nm1;

        // ---- rescale O accum
#pragma unroll
        for (int nt = 0; nt < 16; nt++) {
            o[nt][0] *= al0; o[nt][1] *= al0;
            o[nt][2] *= al1; o[nt][3] *= al1;
        }

        // ---- exp + per-lane row sums
        float s0 = 0.f, s1 = 0.f;
#pragma unroll
        for (int nt = 0; nt < 8; nt++) {
            sacc[nt][0] = exp2f(sacc[nt][0] - nm0);
            sacc[nt][1] = exp2f(sacc[nt][1] - nm0);
            sacc[nt][2] = exp2f(sacc[nt][2] - nm1);
            sacc[nt][3] = exp2f(sacc[nt][3] - nm1);
            s0 += sacc[nt][0] + sacc[nt][1];
            s1 += sacc[nt][2] + sacc[nt][3];
        }
        l0 = l0 * al0 + s0;
        l1 = l1 * al1 + s1;

        // ---- O += P @ V (fp16 k16 mma; P packed from registers)
#pragma unroll
        for (int kc = 0; kc < 4; kc++) {
            uint32_t af[4];
            af[0] = packh2(sacc[2 * kc][0],     sacc[2 * kc][1]);
            af[1] = packh2(sacc[2 * kc][2],     sacc[2 * kc][3]);
            af[2] = packh2(sacc[2 * kc + 1][0], sacc[2 * kc + 1][1]);
            af[3] = packh2(sacc[2 * kc + 1][2], sacc[2 * kc + 1][3]);
            int vkey = kc * 16 + (vmi & 1) * 8 + vrow;
#pragma unroll
            for (int np = 0; np < 16; np += 2) {
                int npp = np + (vmi >> 1);
                uint32_t tmp[4];
                ldsm_x4_trans(tmp, vb + (uint32_t)((npp >> 3) * 8192)
                                      + swz((uint32_t)(vkey * 128 + (npp & 7) * 16)));
                mma_f16(o[np],     af, tmp);
                mma_f16(o[np + 1], af, tmp + 2);
            }
        }
    }

    // ---- epilogue: reduce l, divide, pack fp16, store
    l0 += __shfl_xor_sync(0xffffffffu, l0, 1);
    l0 += __shfl_xor_sync(0xffffffffu, l0, 2);
    l1 += __shfl_xor_sync(0xffffffffu, l1, 1);
    l1 += __shfl_xor_sync(0xffffffffu, l1, 2);
    float il0 = 1.f / l0, il1 = 1.f / l1;
    __half* Ob = Oh + ((size_t)(b * Tn + qb * FM + wid * 16)) * DMODEL + h * HD;
#pragma unroll
    for (int nt = 0; nt < 16; nt++) {
        int col = nt * 8 + cq2;
        uint32_t w0 = packh2(o[nt][0] * il0, o[nt][1] * il0);
        uint32_t w1 = packh2(o[nt][2] * il1, o[nt][3] * il1);
        *(uint32_t*)(Ob + (size_t)g * DMODEL + col)       = w0;
        *(uint32_t*)(Ob + (size_t)(g + 8) * DMODEL + col) = w1;
    }
}

// ---------------- launch ----------------
extern "C" void kernel_launch(void* const* d_in, const int* in_sizes, int n_in,
                              void* d_out, int out_size) {
    (void)in_sizes; (void)n_in; (void)out_size;
    const float* x  = (const float*)d_in[0];
    const float* wq = (const float*)d_in[1];
    const float* wk = (const float*)d_in[2];
    const float* wv = (const float*)d_in[3];
    const float* wo = (const float*)d_in[4];
    float* out = (float*)d_out;

    __half *xh, *QKVh, *Vh, *Oh, *wTh, *woTh;
    cudaGetSymbolAddress((void**)&xh,   g_xh);
    cudaGetSymbolAddress((void**)&QKVh, g_QKVh);
    cudaGetSymbolAddress((void**)&Vh,   g_Vh);
    cudaGetSymbolAddress((void**)&Oh,   g_Oh);
    cudaGetSymbolAddress((void**)&wTh,  g_wTh);
    cudaGetSymbolAddress((void**)&woTh, g_woTh);

    cudaFuncSetAttribute(flash_mma,   cudaFuncAttributeMaxDynamicSharedMemorySize, FLASH_SMEM);
    cudaFuncSetAttribute(gemm_mma<0>, cudaFuncAttributeMaxDynamicSharedMemorySize, GEMM_SMEM);
    cudaFuncSetAttribute(gemm_mma<1>, cudaFuncAttributeMaxDynamicSharedMemorySize, GEMM_SMEM);

    // prep: weight transposes (fp16 K-major) + x fp16 + invf
    prep_kernel<<<PREP_BLOCKS, 256>>>(x, wq, wk, wv, wo, xh, wTh, woTh);

    // Fused QKV projection; epilogue writes fp16 QKVh + scattered fp16 Vh
    gemm_mma<1><<<dim3(QKVSTR / BN, ROWS / BM), 256, GEMM_SMEM>>>(xh, wTh, QKVh, QKVSTR);

    // RoPE in place on fp16 Q,K
    rope_kernel<<<ROPE_BLOCKS, 256>>>(QKVh);

    // Causal attention (FM=64, 2 CTAs/SM)
    flash_mma<<<dim3(Tn / FM, NH, Bn), FTHREADS, FLASH_SMEM>>>(QKVh, Vh, Oh);

    // Output projection (fp32 out)
    gemm_mma<0><<<dim3(DMODEL / BN, ROWS / BM), 256, GEMM_SMEM>>>(Oh, woTh, out, DMODEL);
}

// round 12
// speedup vs baseline: 2.0136x; 1.0098x over previous
#include <cuda_runtime.h>
#include <cuda_fp16.h>
#include <math.h>
#include <stdint.h>

// ---------------- problem constants ----------------
#define Bn 2
#define Tn 2048
#define NH 16
#define NKV 4
#define HD 128
#define DMODEL 2048
#define KVDIM 512
#define QKVSTR 3072         // combined QKV row: Q[0:2048) K[2048:2560) V[2560:3072)
#define ROWS 4096           // Bn*Tn
#define GK 2048             // K dim of every GEMM

// ---------------- scratch (__device__ globals) ----------------
__device__ __half g_xh  [(size_t)ROWS * DMODEL];  // fp16 x
__device__ __half g_QKVh[(size_t)ROWS * QKVSTR];  // fp16 Q,K (roped in place); V region unused
__device__ __half g_Vh  [(size_t)ROWS * KVDIM];   // V fp16: [b][kvh][t][d]
__device__ __half g_Oh  [(size_t)ROWS * DMODEL];  // flash output fp16
__device__ __half g_wTh [(size_t)QKVSTR * GK];    // fused [wq;wk;wv] [N,K] K-major fp16
__device__ __half g_woTh[(size_t)DMODEL * GK];
__device__ float  g_invf[64];

// ---------------- PTX helpers (baseline sm_80+ only) ----------------
__device__ __forceinline__ uint32_t smem_u32(const void* p) {
    uint32_t a;
    asm("{ .reg .u64 t; cvta.to.shared.u64 t, %1; cvt.u32.u64 %0, t; }" : "=r"(a) : "l"(p));
    return a;
}
__device__ __forceinline__ uint32_t packh2(float lo, float hi) {   // {lo,hi} fp16x2 (lo = low half)
    uint32_t r; asm("cvt.rn.f16x2.f32 %0, %1, %2;" : "=r"(r) : "f"(hi), "f"(lo)); return r;
}
__device__ __forceinline__ uint32_t ex2h2(uint32_t x) {            // 2^x on both halves
    uint32_t r; asm("ex2.approx.f16x2 %0, %1;" : "=r"(r) : "r"(x)); return r;
}
__device__ __forceinline__ uint32_t swz(uint32_t off) {   // SW128: bits[6:4] ^= bits[9:7]
    return off ^ ((off >> 3) & 0x70);
}
__device__ __forceinline__ void cp16(uint32_t dst, const void* src) {
    asm volatile("cp.async.cg.shared.global [%0], [%1], 16;" :: "r"(dst), "l"(src) : "memory");
}
#define CP_COMMIT() asm volatile("cp.async.commit_group;" ::: "memory")
#define CP_WAIT(n)  asm volatile("cp.async.wait_group %0;" :: "n"(n) : "memory")

__device__ __forceinline__ void ldsm_x4(uint32_t* r, uint32_t addr) {
    asm volatile("ldmatrix.sync.aligned.m8n8.x4.shared.b16 {%0,%1,%2,%3}, [%4];"
                 : "=r"(r[0]), "=r"(r[1]), "=r"(r[2]), "=r"(r[3]) : "r"(addr));
}
__device__ __forceinline__ void ldsm_x4_trans(uint32_t* r, uint32_t addr) {
    asm volatile("ldmatrix.sync.aligned.m8n8.x4.trans.shared.b16 {%0,%1,%2,%3}, [%4];"
                 : "=r"(r[0]), "=r"(r[1]), "=r"(r[2]), "=r"(r[3]) : "r"(addr));
}
__device__ __forceinline__ void mma_f16(float* d, const uint32_t* a, const uint32_t* b) {
    asm volatile(
        "mma.sync.aligned.m16n8k16.row.col.f32.f16.f16.f32 "
        "{%0,%1,%2,%3}, {%4,%5,%6,%7}, {%8,%9}, {%0,%1,%2,%3};"
        : "+f"(d[0]), "+f"(d[1]), "+f"(d[2]), "+f"(d[3])
        : "r"(a[0]), "r"(a[1]), "r"(a[2]), "r"(a[3]), "r"(b[0]), "r"(b[1]));
}

// ---------------- fused prep kernel ----------------
#define TR_BLOCKS 10240
#define RND_BLOCKS 8192
#define PREP_BLOCKS (TR_BLOCKS + RND_BLOCKS + 1)

__global__ void prep_kernel(const float* __restrict__ x,
                            const float* __restrict__ wq, const float* __restrict__ wk,
                            const float* __restrict__ wv, const float* __restrict__ wo,
                            __half* __restrict__ xh, __half* __restrict__ wTh,
                            __half* __restrict__ woTh) {
    __shared__ float t[32][33];
    int blk = blockIdx.x;
    int tid = threadIdx.x;
    if (blk < TR_BLOCKS) {
        int tx = tid & 31, ty = tid >> 5;
        int bx = blk % 160, kb = blk / 160;
        const float* src; __half* dst; int N;
        if (bx < 64)       { src = wq; dst = wTh;                     N = 2048; }
        else if (bx < 80)  { src = wk; dst = wTh + (size_t)2048 * GK; N = 512;  bx -= 64; }
        else if (bx < 96)  { src = wv; dst = wTh + (size_t)2560 * GK; N = 512;  bx -= 80; }
        else               { src = wo; dst = woTh;                    N = 2048; bx -= 96; }
        int n0 = bx * 32, k0 = kb * 32;
#pragma unroll
        for (int i = ty; i < 32; i += 8)
            t[i][tx] = src[(size_t)(k0 + i) * N + n0 + tx];
        __syncthreads();
#pragma unroll
        for (int i = ty; i < 32; i += 8)
            dst[(size_t)(n0 + i) * GK + k0 + tx] = __float2half_rn(t[tx][i]);
    } else if (blk < TR_BLOCKS + RND_BLOCKS) {
        int i = (blk - TR_BLOCKS) * 256 + tid;     // float4 index
        float4 v = ((const float4*)x)[i];
        uint2 u;
        u.x = packh2(v.x, v.y);
        u.y = packh2(v.z, v.w);
        ((uint2*)xh)[i] = u;
    } else {
        if (tid < 64) g_invf[tid] = (float)exp(-((double)tid / 64.0) * log(10000.0));
    }
}

// ---------------- rope (in-place on fp16 QKVh, Q and K regions) -----------
#define ROPE_TOTQ (ROWS * NH * 64)
#define ROPE_TOTK (ROWS * NKV * 64)
#define ROPE_BLOCKS 20480

__global__ void rope_kernel(__half* __restrict__ QKVh) {
    int idx = blockIdx.x * 256 + threadIdx.x;
    int off; int nheads;
    if (idx < ROPE_TOTQ) { off = 0; nheads = NH; }
    else { idx -= ROPE_TOTQ; off = 2048; nheads = NKV; }
    int d    = idx & 63;
    int rest = idx >> 6;
    int hh   = rest % nheads;
    int row  = rest / nheads;
    int tt   = row & (Tn - 1);
    float ang = (float)tt * g_invf[d];
    float sn, cs;
    sincosf(ang, &sn, &cs);
    __half* p = QKVh + (size_t)row * QKVSTR + off + hh * HD + d;
    float x0 = __half2float(p[0]), x1 = __half2float(p[64]);
    p[0]  = __float2half_rn(x0 * cs - x1 * sn);
    p[64] = __float2half_rn(x1 * cs + x0 * sn);
}

// ---------------- fp16 mma.sync GEMM (occupancy 2) ----------------
#define BM 128
#define BN 128
#define NSTG 3
#define ASTG 16384
#define BSTG 16384
#define STG  (ASTG + BSTG)
#define GEMM_SMEM (NSTG * STG)   // 98304
#define KITERS 32             // 2048 / 64

template <int MODE>
__global__ __launch_bounds__(256, 2)
void gemm_mma(const __half* __restrict__ A, const __half* __restrict__ Bt,
              void* __restrict__ Cout, int N) {
    extern __shared__ char dsm[];
    const uint32_t base = smem_u32(dsm);

    const int tid  = threadIdx.x;
    const int wid  = tid >> 5;
    const int lane = tid & 31;
    const int mb   = blockIdx.y * BM;
    const int nb   = blockIdx.x * BN;
    const int wm   = (wid & 1) * 64;
    const int wn   = (wid >> 1) * 32;

    const __half* Ag = A  + (size_t)mb * GK;
    const __half* Bg = Bt + (size_t)nb * GK;

    float acc[4][4][4];
#pragma unroll
    for (int mt = 0; mt < 4; mt++)
#pragma unroll
        for (int nt = 0; nt < 4; nt++)
#pragma unroll
            for (int q = 0; q < 4; q++) acc[mt][nt][q] = 0.f;

    auto issue = [&](int buf, int s) {
        uint32_t sa = base + (uint32_t)buf * STG;
        uint32_t sb = sa + ASTG;
        int k0 = s * 64;
#pragma unroll
        for (int i = 0; i < 4; i++) {
            int cc  = tid + i * 256;
            int row = cc >> 3, ch = cc & 7;
            uint32_t off = swz((uint32_t)(row * 128 + ch * 16));
            cp16(sa + off, Ag + (size_t)row * GK + k0 + ch * 8);
            cp16(sb + off, Bg + (size_t)row * GK + k0 + ch * 8);
        }
        CP_COMMIT();
    };

    issue(0, 0); issue(1, 1);

    const int a_r  = (lane & 7) + ((lane >> 3) & 1) * 8;
    const int a_kc = (lane >> 4);
    const int b_r  = (lane & 7) + (lane >> 4) * 8;
    const int b_kc = ((lane >> 3) & 1);

    int st = 0, stp = 2;
    for (int s = 0; s < KITERS; s++) {
        if (s + 2 < KITERS) CP_WAIT(1); else CP_WAIT(0);
        __syncthreads();
        if (s + 2 < KITERS) issue(stp, s + 2);

        uint32_t sa = base + (uint32_t)st * STG + (uint32_t)(wm * 128);
        uint32_t sb = base + (uint32_t)st * STG + ASTG + (uint32_t)(wn * 128);

#pragma unroll
        for (int ks = 0; ks < 4; ks++) {
            uint32_t afr[4][4];
            uint32_t bfr[4][2];
#pragma unroll
            for (int mt = 0; mt < 4; mt++)
                ldsm_x4(afr[mt], sa + swz((uint32_t)((mt * 16 + a_r) * 128 + (2 * ks + a_kc) * 16)));
            {
                uint32_t tmp[4];
                ldsm_x4(tmp, sb + swz((uint32_t)((b_r) * 128 + (2 * ks + b_kc) * 16)));
                bfr[0][0] = tmp[0]; bfr[0][1] = tmp[1];
                bfr[1][0] = tmp[2]; bfr[1][1] = tmp[3];
                ldsm_x4(tmp, sb + swz((uint32_t)((16 + b_r) * 128 + (2 * ks + b_kc) * 16)));
                bfr[2][0] = tmp[0]; bfr[2][1] = tmp[1];
                bfr[3][0] = tmp[2]; bfr[3][1] = tmp[3];
            }
#pragma unroll
            for (int mt = 0; mt < 4; mt++)
#pragma unroll
                for (int nt = 0; nt < 4; nt++)
                    mma_f16(acc[mt][nt], afr[mt], bfr[nt]);
        }
        st  = (st  == NSTG - 1) ? 0 : st + 1;
        stp = (stp == NSTG - 1) ? 0 : stp + 1;
    }

    const int g = lane >> 2;
    const int cq = (lane & 3) * 2;
#pragma unroll
    for (int mt = 0; mt < 4; mt++) {
        int row0 = mb + wm + mt * 16 + g;
#pragma unroll
        for (int nt = 0; nt < 4; nt++) {
            int col = nb + wn + nt * 8 + cq;
            if (MODE == 0) {
                float* C = (float*)Cout;
                *(float2*)(C + (size_t)row0 * N + col)       = make_float2(acc[mt][nt][0], acc[mt][nt][1]);
                *(float2*)(C + (size_t)(row0 + 8) * N + col) = make_float2(acc[mt][nt][2], acc[mt][nt][3]);
            } else {
                uint32_t w0 = packh2(acc[mt][nt][0], acc[mt][nt][1]);
                uint32_t w1 = packh2(acc[mt][nt][2], acc[mt][nt][3]);
                if (col < 2560) {
                    __half* C = (__half*)Cout;
                    *(uint32_t*)(C + (size_t)row0 * QKVSTR + col)       = w0;
                    *(uint32_t*)(C + (size_t)(row0 + 8) * QKVSTR + col) = w1;
                } else {
                    int rel = col - 2560;
                    int kvh = rel >> 7, d = rel & 127;
                    int b0 = row0 >> 11, t0 = row0 & (Tn - 1);
                    int b1 = (row0 + 8) >> 11, t1 = (row0 + 8) & (Tn - 1);
                    *(uint32_t*)(g_Vh + (((size_t)(b0 * NKV + kvh) * Tn + t0) * HD + d)) = w0;
                    *(uint32_t*)(g_Vh + (((size_t)(b1 * NKV + kvh) * Tn + t1) * HD + d)) = w1;
                }
            }
        }
    }
}

// ---------------- flash attention: f16x2 exp + mma row-sums ---------------
#define FM 64
#define FN 64
#define KVBUF 32768
#define FLASH_SMEM (16384 + 2 * KVBUF)   // 81920
#define FTHREADS 128

__global__ __launch_bounds__(FTHREADS, 2)
void flash_mma(const __half* __restrict__ QKVh, const __half* __restrict__ Vh,
               __half* __restrict__ Oh) {
    extern __shared__ float sm[];
    const uint32_t base = smem_u32(sm);
    const int tid = threadIdx.x, wid = tid >> 5, lane = tid & 31;
    const int qb = (Tn / FM - 1) - blockIdx.x;   // heavy blocks first
    const int h = blockIdx.y, b = blockIdx.z;
    const int kvh = h >> 2;
    const int nkt = qb + 1;

    const __half* Qg = QKVh + ((size_t)(b * Tn + qb * FM)) * QKVSTR + h * HD;
    const __half* Kg = QKVh + ((size_t)(b * Tn)) * QKVSTR + 2048 + kvh * HD;
    const __half* Vg = Vh + ((size_t)(b * NKV + kvh)) * Tn * HD;

    // ---- Q tile: 1024 16B chunks
#pragma unroll
    for (int i = 0; i < 8; i++) {
        int f = tid + i * FTHREADS;
        int qr = f >> 4, ch = f & 15;
        cp16(base + (uint32_t)((ch >> 3) * 8192) + swz((uint32_t)(qr * 128 + (ch & 7) * 16)),
             Qg + (size_t)qr * QKVSTR + ch * 8);
    }

    auto kv_issue = [&](int kt) {
        uint32_t kb = base + 16384u + (uint32_t)(kt & 1) * KVBUF;
        uint32_t vb = kb + 16384u;
        const __half* Ksrc = Kg + (size_t)(kt * FN) * QKVSTR;
        const __half* Vsrc = Vg + (size_t)(kt * FN) * HD;
#pragma unroll
        for (int i = 0; i < 8; i++) {
            int f = tid + i * FTHREADS;
            int kr = f >> 4, ch = f & 15;
            cp16(kb + (uint32_t)((ch >> 3) * 8192) + swz((uint32_t)(kr * 128 + (ch & 7) * 16)),
                 Ksrc + (size_t)kr * QKVSTR + ch * 8);
        }
#pragma unroll
        for (int i = 0; i < 8; i++) {
            int f = tid + i * FTHREADS;
            int key = f >> 4, ch = f & 15;
            cp16(vb + (uint32_t)((ch >> 3) * 8192) + swz((uint32_t)(key * 128 + (ch & 7) * 16)),
                 Vsrc + key * HD + ch * 8);
        }
        CP_COMMIT();
    };

    const int a_r  = (lane & 7) + ((lane >> 3) & 1) * 8;
    const int a_kc = lane >> 4;
    const int b_r  = (lane & 7) + (lane >> 4) * 8;
    const int b_kc = (lane >> 3) & 1;
    const int g    = lane >> 2;
    const int cq2  = (lane & 3) * 2;
    const int vrow = lane & 7;
    const int vmi  = lane >> 3;
    const float scale2 = 0.08838834764831843f * 1.4426950408889634f;
    const uint32_t ONESx2 = 0x3C003C00u;   // {1.0h, 1.0h}
    const uint32_t bones[2] = {ONESx2, ONESx2};

    float o[16][4];
#pragma unroll
    for (int nt = 0; nt < 16; nt++)
#pragma unroll
        for (int q = 0; q < 4; q++) o[nt][q] = 0.f;
    float lacc[4] = {0.f, 0.f, 0.f, 0.f};   // mma row-sum accumulator (l)
    float m0 = -1e30f, m1 = -1e30f;

    kv_issue(0);   // commits Q + kv0 as group 0

    for (int kt = 0; kt < nkt; kt++) {
        __syncthreads();
        if (kt + 1 < nkt) { kv_issue(kt + 1); CP_WAIT(1); }
        else              { CP_WAIT(0); }
        __syncthreads();

        uint32_t kb = base + 16384u + (uint32_t)(kt & 1) * KVBUF;
        uint32_t vb = kb + 16384u;

        // ---- S = Q @ K^T (fp16, 8 x k16)
        float sacc[8][4];
#pragma unroll
        for (int nt = 0; nt < 8; nt++)
#pragma unroll
            for (int q = 0; q < 4; q++) sacc[nt][q] = 0.f;

#pragma unroll
        for (int ks = 0; ks < 8; ks++) {
            uint32_t af[4];
            ldsm_x4(af, base + (uint32_t)((ks >> 2) * 8192)
                        + swz((uint32_t)((wid * 16 + a_r) * 128 + ((ks & 3) * 2 + a_kc) * 16)));
            uint32_t bf[8][2];
#pragma unroll
            for (int np = 0; np < 4; np++) {
                uint32_t tmp[4];
                ldsm_x4(tmp, kb + (uint32_t)((ks >> 2) * 8192)
                             + swz((uint32_t)((np * 16 + b_r) * 128 + ((ks & 3) * 2 + b_kc) * 16)));
                bf[np * 2][0] = tmp[0]; bf[np * 2][1] = tmp[1];
                bf[np * 2 + 1][0] = tmp[2]; bf[np * 2 + 1][1] = tmp[3];
            }
#pragma unroll
            for (int nt = 0; nt < 8; nt++) mma_f16(sacc[nt], af, bf[nt]);
        }

        // ---- scale + causal mask (diagonal tile only)
        if (kt == qb) {
            int rl0 = wid * 16 + g, rl1 = rl0 + 8;
#pragma unroll
            for (int nt = 0; nt < 8; nt++) {
                int kc0 = nt * 8 + cq2;
                sacc[nt][0] = (kc0     > rl0) ? -1e30f : sacc[nt][0] * scale2;
                sacc[nt][1] = (kc0 + 1 > rl0) ? -1e30f : sacc[nt][1] * scale2;
                sacc[nt][2] = (kc0     > rl1) ? -1e30f : sacc[nt][2] * scale2;
                sacc[nt][3] = (kc0 + 1 > rl1) ? -1e30f : sacc[nt][3] * scale2;
            }
        } else {
#pragma unroll
            for (int nt = 0; nt < 8; nt++)
#pragma unroll
                for (int q = 0; q < 4; q++) sacc[nt][q] *= scale2;
        }

        // ---- row max + alpha
        float mx0 = -1e30f, mx1 = -1e30f;
#pragma unroll
        for (int nt = 0; nt < 8; nt++) {
            mx0 = fmaxf(mx0, fmaxf(sacc[nt][0], sacc[nt][1]));
            mx1 = fmaxf(mx1, fmaxf(sacc[nt][2], sacc[nt][3]));
        }
        mx0 = fmaxf(mx0, __shfl_xor_sync(0xffffffffu, mx0, 1));
        mx0 = fmaxf(mx0, __shfl_xor_sync(0xffffffffu, mx0, 2));
        mx1 = fmaxf(mx1, __shfl_xor_sync(0xffffffffu, mx1, 1));
        mx1 = fmaxf(mx1, __shfl_xor_sync(0xffffffffu, mx1, 2));
        float nm0 = fmaxf(m0, mx0), nm1 = fmaxf(m1, mx1);
        float al0 = exp2f(m0 - nm0), al1 = exp2f(m1 - nm1);
        m0 = nm0; m1 = nm1;

        // ---- P = 2^(s-nm) computed directly in fp16x2 (MUFU halved);
        //      pf[kc][0..3] IS the PV A-fragment.
        uint32_t pf[4][4];
#pragma unroll
        for (int kc = 0; kc < 4; kc++) {
            pf[kc][0] = ex2h2(packh2(sacc[2 * kc][0] - nm0,     sacc[2 * kc][1] - nm0));
            pf[kc][1] = ex2h2(packh2(sacc[2 * kc][2] - nm1,     sacc[2 * kc][3] - nm1));
            pf[kc][2] = ex2h2(packh2(sacc[2 * kc + 1][0] - nm0, sacc[2 * kc + 1][1] - nm0));
            pf[kc][3] = ex2h2(packh2(sacc[2 * kc + 1][2] - nm1, sacc[2 * kc + 1][3] - nm1));
        }

        // ---- rescale O + l accumulators
#pragma unroll
        for (int nt = 0; nt < 16; nt++) {
            o[nt][0] *= al0; o[nt][1] *= al0;
            o[nt][2] *= al1; o[nt][3] *= al1;
        }
        lacc[0] *= al0; lacc[1] *= al0;
        lacc[2] *= al1; lacc[3] *= al1;

        // ---- l += P @ ones (exact fp32 row-sums of the fp16 P)
#pragma unroll
        for (int kc = 0; kc < 4; kc++) mma_f16(lacc, pf[kc], bones);

        // ---- O += P @ V
#pragma unroll
        for (int kc = 0; kc < 4; kc++) {
            int vkey = kc * 16 + (vmi & 1) * 8 + vrow;
#pragma unroll
            for (int np = 0; np < 16; np += 2) {
                int npp = np + (vmi >> 1);
                uint32_t tmp[4];
                ldsm_x4_trans(tmp, vb + (uint32_t)((npp >> 3) * 8192)
                                      + swz((uint32_t)(vkey * 128 + (npp & 7) * 16)));
                mma_f16(o[np],     pf[kc], tmp);
                mma_f16(o[np + 1], pf[kc], tmp + 2);
            }
        }
    }

    // ---- epilogue: l complete per-thread (B=ones -> every n col = rowsum)
    float il0 = 1.f / lacc[0], il1 = 1.f / lacc[2];
    __half* Ob = Oh + ((size_t)(b * Tn + qb * FM + wid * 16)) * DMODEL + h * HD;
#pragma unroll
    for (int nt = 0; nt < 16; nt++) {
        int col = nt * 8 + cq2;
        uint32_t w0 = packh2(o[nt][0] * il0, o[nt][1] * il0);
        uint32_t w1 = packh2(o[nt][2] * il1, o[nt][3] * il1);
        *(uint32_t*)(Ob + (size_t)g * DMODEL + col)       = w0;
        *(uint32_t*)(Ob + (size_t)(g + 8) * DMODEL + col) = w1;
    }
}

// ---------------- launch ----------------
extern "C" void kernel_launch(void* const* d_in, const int* in_sizes, int n_in,
                              void* d_out, int out_size) {
    (void)in_sizes; (void)n_in; (void)out_size;
    const float* x  = (const float*)d_in[0];
    const float* wq = (const float*)d_in[1];
    const float* wk = (const float*)d_in[2];
    const float* wv = (const float*)d_in[3];
    const float* wo = (const float*)d_in[4];
    float* out = (float*)d_out;

    __half *xh, *QKVh, *Vh, *Oh, *wTh, *woTh;
    cudaGetSymbolAddress((void**)&xh,   g_xh);
    cudaGetSymbolAddress((void**)&QKVh, g_QKVh);
    cudaGetSymbolAddress((void**)&Vh,   g_Vh);
    cudaGetSymbolAddress((void**)&Oh,   g_Oh);
    cudaGetSymbolAddress((void**)&wTh,  g_wTh);
    cudaGetSymbolAddress((void**)&woTh, g_woTh);

    cudaFuncSetAttribute(flash_mma,   cudaFuncAttributeMaxDynamicSharedMemorySize, FLASH_SMEM);
    cudaFuncSetAttribute(gemm_mma<0>, cudaFuncAttributeMaxDynamicSharedMemorySize, GEMM_SMEM);
    cudaFuncSetAttribute(gemm_mma<1>, cudaFuncAttributeMaxDynamicSharedMemorySize, GEMM_SMEM);

    // prep: weight transposes (fp16 K-major) + x fp16 + invf
    prep_kernel<<<PREP_BLOCKS, 256>>>(x, wq, wk, wv, wo, xh, wTh, woTh);

    // Fused QKV projection; epilogue writes fp16 QKVh + scattered fp16 Vh
    gemm_mma<1><<<dim3(QKVSTR / BN, ROWS / BM), 256, GEMM_SMEM>>>(xh, wTh, QKVh, QKVSTR);

    // RoPE in place on fp16 Q,K
    rope_kernel<<<ROPE_BLOCKS, 256>>>(QKVh);

    // Causal attention
    flash_mma<<<dim3(Tn / FM, NH, Bn), FTHREADS, FLASH_SMEM>>>(QKVh, Vh, Oh);

    // Output projection (fp32 out)
    gemm_mma<0><<<dim3(DMODEL / BN, ROWS / BM), 256, GEMM_SMEM>>>(Oh, woTh, out, DMODEL);
}